// round 15
// baseline (speedup 1.0000x reference)
#include <cuda_runtime.h>
#include <cuda_bf16.h>
#include <cuda_fp16.h>
#include <cfloat>
#include <cstdint>

#define N_NODES 50000
#define N_EDGES 800000
#define HID 64
#define ZDIM 320
#define WSTRIDE 68                 // padded W row (64x68, zeros in pad)
#define WSZ (64 * WSTRIDE)
#define SCAN_BLK 98                // ceil(50000/512)
#define NPADZ 50016                // pad g_z rows for 32-node MLP tiles

typedef unsigned long long ull;
typedef uint32_t u32;

// ---------------- device scratch ----------------
__device__ __half g_uh[N_NODES * HID];     // u stored fp16 (gather payload)
__device__ float g_z[NPADZ * ZDIM];        // pad rows never written -> zero
__device__ int   g_cnt[N_NODES];           // INVARIANT: all-zero at kernel_launch entry
__device__ int   g_off[N_NODES + 1];
__device__ int   g_cur[N_NODES];
__device__ int   g_csr[N_EDGES];
__device__ int   g_bsum[SCAN_BLK];
__device__ int   g_dcnt[128];              // INVARIANT: all-zero at entry (re-zeroed in k_dscan)
__device__ int   g_dcur[128];
__device__ int   g_perm[N_NODES];          // nodes sorted by degree
__device__ float g_Wq[5 * WSZ];            // all 5 quantized layer weights
// HMMA fragment-ordered weights (hi/lo fp16 split):
__device__ uint2 g_w1f_h[20 * 16 * 32], g_w1f_l[20 * 16 * 32];   // 320->128
__device__ uint2 g_w2f_h[8 * 16 * 32],  g_w2f_l[8 * 16 * 32];    // 128->128
__device__ uint2 g_w3f_h[8 * 8 * 32],   g_w3f_l[8 * 8 * 32];     // 128->64

// ---------------- f32x2 helpers ----------------
__device__ __forceinline__ ull fma2(ull a, ull b, ull c) {
    ull d;
    asm("fma.rn.f32x2 %0, %1, %2, %3;" : "=l"(d) : "l"(a), "l"(b), "l"(c));
    return d;
}
__device__ __forceinline__ float sum2(ull a) {
    float lo, hi;
    asm("mov.b64 {%0, %1}, %2;" : "=f"(lo), "=f"(hi) : "l"(a));
    return lo + hi;
}

// ---------------- mma.sync m16n8k16 f16 helper ----------------
__device__ __forceinline__ void mma16816(float* d, u32 a0, u32 a1, u32 a2, u32 a3,
                                         u32 b0, u32 b1) {
    asm volatile(
        "mma.sync.aligned.m16n8k16.row.col.f32.f16.f16.f32 "
        "{%0,%1,%2,%3}, {%4,%5,%6,%7}, {%8,%9}, {%0,%1,%2,%3};"
        : "+f"(d[0]), "+f"(d[1]), "+f"(d[2]), "+f"(d[3])
        : "r"(a0), "r"(a1), "r"(a2), "r"(a3), "r"(b0), "r"(b1));
}

__device__ __forceinline__ u32 packh2(float a, float b) {
    __half2 h = __floats2half2_rn(a, b);
    return *(u32*)&h;
}

// ---------------- prep: hist (0..3124) + fake-quant (3125..3129) + fragments (3130..3193) ----------------
__global__ void k_prep(const int* __restrict__ ei,
                       const float* __restrict__ W0, const float* __restrict__ Ws,
                       const float* __restrict__ w1, const float* __restrict__ w2,
                       const float* __restrict__ w3) {
    int blk = blockIdx.x, tid = threadIdx.x;
    if (blk < 3125) {
        int e = blk * 256 + tid;
        if (e < N_EDGES) atomicAdd(&g_cnt[ei[N_EDGES + e]], 1);
        return;
    }
    if (blk < 3130) {
        int b = blk - 3125;
        __shared__ float red[256];
        const float* W = (b == 0) ? W0 : (Ws + (size_t)(b - 1) * 64 * 67);
        int cols = (b == 0) ? 4 : 67;
        int n = 64 * cols;
        float* dst = g_Wq + b * WSZ;

        float m = 0.f;
        for (int i = tid; i < n; i += 256) m = fmaxf(m, fabsf(W[i]));
        red[tid] = m;
        __syncthreads();
        for (int s = 128; s > 0; s >>= 1) {
            if (tid < s) red[tid] = fmaxf(red[tid], red[tid + s]);
            __syncthreads();
        }
        float sc = fmaxf(red[0] * (1.0f / 127.0f), 1e-8f);
        for (int i = tid; i < WSZ; i += 256) dst[i] = 0.0f;
        __syncthreads();
        for (int i = tid; i < n; i += 256) {
            int k = i / cols, c = i % cols;
            float q = rintf(W[i] / sc);
            q = fminf(fmaxf(q, -127.0f), 127.0f) * sc;
            dst[k * WSTRIDE + c] = q;
        }
        return;
    }
    int idx = (blk - 3130) * 256 + tid;
    const float* src;
    uint2 *dh, *dl;
    int K, slot;
    if (idx < 10240)      { src = w1; dh = g_w1f_h; dl = g_w1f_l; K = 320; slot = idx;
                            int kt = slot >> 9, rem = slot & 511, nb = rem >> 5, lane = rem & 31;
                            int g = lane >> 2, tq = lane & 3;
                            int n = nb * 8 + g, kb = kt * 16 + tq * 2;
                            float v0 = src[n * K + kb],     v1 = src[n * K + kb + 1];
                            float v2 = src[n * K + kb + 8], v3 = src[n * K + kb + 9];
                            __half h0 = __float2half(v0), h1 = __float2half(v1);
                            __half h2 = __float2half(v2), h3 = __float2half(v3);
                            dh[slot] = make_uint2(packh2(__half2float(h0), __half2float(h1)),
                                                  packh2(__half2float(h2), __half2float(h3)));
                            dl[slot] = make_uint2(packh2(v0 - __half2float(h0), v1 - __half2float(h1)),
                                                  packh2(v2 - __half2float(h2), v3 - __half2float(h3)));
    } else if (idx < 14336) { src = w2; dh = g_w2f_h; dl = g_w2f_l; K = 128; slot = idx - 10240;
                            int kt = slot >> 9, rem = slot & 511, nb = rem >> 5, lane = rem & 31;
                            int g = lane >> 2, tq = lane & 3;
                            int n = nb * 8 + g, kb = kt * 16 + tq * 2;
                            float v0 = src[n * K + kb],     v1 = src[n * K + kb + 1];
                            float v2 = src[n * K + kb + 8], v3 = src[n * K + kb + 9];
                            __half h0 = __float2half(v0), h1 = __float2half(v1);
                            __half h2 = __float2half(v2), h3 = __float2half(v3);
                            dh[slot] = make_uint2(packh2(__half2float(h0), __half2float(h1)),
                                                  packh2(__half2float(h2), __half2float(h3)));
                            dl[slot] = make_uint2(packh2(v0 - __half2float(h0), v1 - __half2float(h1)),
                                                  packh2(v2 - __half2float(h2), v3 - __half2float(h3)));
    } else if (idx < 16384) { src = w3; dh = g_w3f_h; dl = g_w3f_l; K = 128; slot = idx - 14336;
                            int kt = slot >> 8, rem = slot & 255, nb = rem >> 5, lane = rem & 31;
                            int g = lane >> 2, tq = lane & 3;
                            int n = nb * 8 + g, kb = kt * 16 + tq * 2;
                            float v0 = src[n * K + kb],     v1 = src[n * K + kb + 1];
                            float v2 = src[n * K + kb + 8], v3 = src[n * K + kb + 9];
                            __half h0 = __float2half(v0), h1 = __float2half(v1);
                            __half h2 = __float2half(v2), h3 = __float2half(v3);
                            dh[slot] = make_uint2(packh2(__half2float(h0), __half2float(h1)),
                                                  packh2(__half2float(h2), __half2float(h3)));
                            dl[slot] = make_uint2(packh2(v0 - __half2float(h0), v1 - __half2float(h1)),
                                                  packh2(v2 - __half2float(h2), v3 - __half2float(h3)));
    }
}

// ---------------- CSR scan ----------------
__global__ void k_scan_local() {
    __shared__ int wsums[16];
    int b = blockIdx.x, tid = threadIdx.x, lane = tid & 31, wid = tid >> 5;
    int i = b * 512 + tid;
    int v = (i < N_NODES) ? g_cnt[i] : 0;
    int x = v;
    #pragma unroll
    for (int o = 1; o < 32; o <<= 1) {
        int y = __shfl_up_sync(0xffffffffu, x, o);
        if (lane >= o) x += y;
    }
    if (lane == 31) wsums[wid] = x;
    __syncthreads();
    if (wid == 0 && lane < 16) {
        int w = wsums[lane];
        int xs = w;
        #pragma unroll
        for (int o = 1; o < 16; o <<= 1) {
            int y = __shfl_up_sync(0xffffu, xs, o);
            if (lane >= o) xs += y;
        }
        wsums[lane] = xs - w;
    }
    __syncthreads();
    int excl = x - v + wsums[wid];
    if (i < N_NODES) g_off[i] = excl;
    if (tid == 511) g_bsum[b] = excl + v;
}

__global__ void k_scan_add() {
    __shared__ int part[4];
    int b = blockIdx.x, tid = threadIdx.x, lane = tid & 31, wid = tid >> 5;
    int v = 0;
    if (tid < b) v = g_bsum[tid];      // b <= 97 < 128
    if (tid < 128) {
        #pragma unroll
        for (int o = 16; o > 0; o >>= 1) v += __shfl_xor_sync(0xffffffffu, v, o);
        if (lane == 0) part[wid] = v;
    }
    __syncthreads();
    int add = part[0] + part[1] + part[2] + part[3];
    int i = b * 512 + tid;
    if (i < N_NODES) {
        int o = g_off[i] + add;
        g_off[i] = o;
        g_cur[i] = o;
        g_cnt[i] = 0;   // restore zero-invariant for next replay
    }
    if (i == 0) g_off[N_NODES] = N_EDGES;
}

// scatter edges + piggybacked degree histogram (node-range threads)
__global__ void k_scatter(const int* __restrict__ ei) {
    int e = blockIdx.x * blockDim.x + threadIdx.x;
    if (e < N_EDGES) {
        int d = ei[N_EDGES + e];
        int p = atomicAdd(&g_cur[d], 1);
        g_csr[p] = ei[e];
    }
    if (e < N_NODES) {
        int deg = min(g_off[e + 1] - g_off[e], 127);
        atomicAdd(&g_dcnt[deg], 1);
    }
}

// exclusive scan over 128 degree buckets; re-zero g_dcnt
__global__ void k_dscan() {
    __shared__ int ws[4];
    int tid = threadIdx.x, lane = tid & 31, w = tid >> 5;
    int v = g_dcnt[tid];
    g_dcnt[tid] = 0;                   // restore zero-invariant
    int x = v;
    #pragma unroll
    for (int o = 1; o < 32; o <<= 1) {
        int y = __shfl_up_sync(0xffffffffu, x, o);
        if (lane >= o) x += y;
    }
    if (lane == 31) ws[w] = x;
    __syncthreads();
    int add = 0;
    for (int i = 0; i < w; i++) add += ws[i];
    g_dcur[tid] = x - v + add;
}

__global__ void k_dperm() {
    int i = blockIdx.x * blockDim.x + threadIdx.x;
    if (i < N_NODES) {
        int d = min(g_off[i + 1] - g_off[i], 127);
        int p = atomicAdd(&g_dcur[d], 1);
        g_perm[p] = i;
    }
}

// ---------------- layer-0 transform ----------------
__global__ __launch_bounds__(256) void k_transform0(const float* __restrict__ x,
                                                    const float* __restrict__ pos) {
    __shared__ float4 Wsh[64];
    __shared__ float  xs[32];
    __shared__ float  ps[96];
    int tid = threadIdx.x;
    int nbase = blockIdx.x * 32;
    if (tid < 64) {
        const float* wr = g_Wq + tid * WSTRIDE;
        Wsh[tid] = make_float4(wr[0], wr[1], wr[2], wr[3]);
    } else if (tid < 96) {
        int n = nbase + (tid - 64);
        xs[tid - 64] = (n < N_NODES) ? x[n] : 0.f;
    } else if (tid < 192) {
        int j = tid - 96;
        int gi = nbase * 3 + j;
        ps[j] = (gi < N_NODES * 3) ? pos[gi] : 0.f;
    }
    __syncthreads();
    int k = tid & 63, grp = tid >> 6;
    float4 w = Wsh[k];
    #pragma unroll
    for (int j = 0; j < 8; j++) {
        int nn = grp * 8 + j;
        int n = nbase + nn;
        if (n < N_NODES) {
            float r = w.x * xs[nn] + w.y * ps[3 * nn] + w.z * ps[3 * nn + 1] + w.w * ps[3 * nn + 2];
            g_uh[(size_t)n * HID + k] = __float2half(r);
        }
    }
}

// ---------------- layers 1-4 transform ----------------
__global__ __launch_bounds__(256) void k_transform(const float* __restrict__ pos, int layer) {
    constexpr int C4 = 17;
    __shared__ float Wsh[WSZ];
    __shared__ float fsh[32][WSTRIDE];
    int tid = threadIdx.x;
    int k = tid & 63, grp = tid >> 6;
    const float* Wsrc = g_Wq + layer * WSZ;
    {
        const float4* s4 = (const float4*)Wsrc;
        float4* d4 = (float4*)Wsh;
        #pragma unroll
        for (int i = tid; i < WSZ / 4; i += 256) d4[i] = s4[i];
    }
    int nbase = blockIdx.x * 32;
    const float* h = g_z + (size_t)(layer - 1) * HID;
    #pragma unroll
    for (int i = tid; i < 32 * 64; i += 256) {
        int nn = i >> 6, c = i & 63;
        int gn = nbase + nn;
        fsh[nn][c] = (gn < N_NODES) ? h[(size_t)gn * ZDIM + c] : 0.f;
    }
    if (tid < 128) {
        int nn = tid >> 2, j = tid & 3;
        int gn = nbase + nn;
        float v = 0.f;
        if (j < 3 && gn < N_NODES) v = pos[gn * 3 + j];
        fsh[nn][64 + j] = v;
    }
    __syncthreads();
    ull w2r[C4 * 2];
    #pragma unroll
    for (int c4 = 0; c4 < C4; c4++) {
        ulonglong2 wv = *(const ulonglong2*)&Wsh[k * WSTRIDE + 4 * c4];
        w2r[2 * c4] = wv.x; w2r[2 * c4 + 1] = wv.y;
    }
    ull acc[8];
    #pragma unroll
    for (int j = 0; j < 8; j++) acc[j] = 0;
    #pragma unroll
    for (int c4 = 0; c4 < C4; c4++) {
        ull w01 = w2r[2 * c4], w23 = w2r[2 * c4 + 1];
        #pragma unroll
        for (int j = 0; j < 8; j++) {
            ulonglong2 f = *(const ulonglong2*)&fsh[grp * 8 + j][4 * c4];
            acc[j] = fma2(f.x, w01, acc[j]);
            acc[j] = fma2(f.y, w23, acc[j]);
        }
    }
    #pragma unroll
    for (int j = 0; j < 8; j++) {
        int n = nbase + grp * 8 + j;
        if (n < N_NODES) g_uh[(size_t)n * HID + k] = __float2half(sum2(acc[j]));
    }
}

// ---------------- aggregation: degree-sorted, 2 nodes/warp, 16 lanes x half2x2 ----------------
__global__ __launch_bounds__(256) void k_aggregate(const float* __restrict__ pos,
                                                   const float* __restrict__ ln_g,
                                                   const float* __restrict__ ln_b,
                                                   int layer, int cols) {
    __shared__ float Wp[64][3];
    __shared__ float gs[64], bs[64];
    int tid = threadIdx.x;
    if (tid < 64) { gs[tid] = ln_g[layer * 64 + tid]; bs[tid] = ln_b[layer * 64 + tid]; }
    const float* Wsrc = g_Wq + layer * WSZ;
    for (int i = tid; i < 192; i += 256) {
        int k = i / 3, j = i % 3;
        Wp[k][j] = Wsrc[k * WSTRIDE + (cols - 3) + j];
    }
    __syncthreads();

    int wid = tid >> 5, lane = tid & 31;
    int half = lane >> 4, l16 = lane & 15;
    int n = g_perm[blockIdx.x * 16 + wid * 2 + half];   // degree-sorted node
    int s = g_off[n], e = g_off[n + 1];
    const uint2* ubase = (const uint2*)g_uh;

    __half2 M0 = __float2half2_rn(-65504.f);
    __half2 M1 = __float2half2_rn(-65504.f);
    int p = s;
    for (; p + 8 <= e; p += 8) {
        int i0 = g_csr[p],     i1 = g_csr[p + 1], i2 = g_csr[p + 2], i3 = g_csr[p + 3];
        int i4 = g_csr[p + 4], i5 = g_csr[p + 5], i6 = g_csr[p + 6], i7 = g_csr[p + 7];
        uint2 a = __ldcg(&ubase[(size_t)i0 * 16 + l16]);
        uint2 b = __ldcg(&ubase[(size_t)i1 * 16 + l16]);
        uint2 c = __ldcg(&ubase[(size_t)i2 * 16 + l16]);
        uint2 d = __ldcg(&ubase[(size_t)i3 * 16 + l16]);
        uint2 f = __ldcg(&ubase[(size_t)i4 * 16 + l16]);
        uint2 g = __ldcg(&ubase[(size_t)i5 * 16 + l16]);
        uint2 h = __ldcg(&ubase[(size_t)i6 * 16 + l16]);
        uint2 q = __ldcg(&ubase[(size_t)i7 * 16 + l16]);
        M0 = __hmax2(M0, __hmax2(__hmax2(*(__half2*)&a.x, *(__half2*)&b.x),
                                 __hmax2(*(__half2*)&c.x, *(__half2*)&d.x)));
        M0 = __hmax2(M0, __hmax2(__hmax2(*(__half2*)&f.x, *(__half2*)&g.x),
                                 __hmax2(*(__half2*)&h.x, *(__half2*)&q.x)));
        M1 = __hmax2(M1, __hmax2(__hmax2(*(__half2*)&a.y, *(__half2*)&b.y),
                                 __hmax2(*(__half2*)&c.y, *(__half2*)&d.y)));
        M1 = __hmax2(M1, __hmax2(__hmax2(*(__half2*)&f.y, *(__half2*)&g.y),
                                 __hmax2(*(__half2*)&h.y, *(__half2*)&q.y)));
    }
    for (; p + 4 <= e; p += 4) {
        int i0 = g_csr[p], i1 = g_csr[p + 1], i2 = g_csr[p + 2], i3 = g_csr[p + 3];
        uint2 a = __ldcg(&ubase[(size_t)i0 * 16 + l16]);
        uint2 b = __ldcg(&ubase[(size_t)i1 * 16 + l16]);
        uint2 c = __ldcg(&ubase[(size_t)i2 * 16 + l16]);
        uint2 d = __ldcg(&ubase[(size_t)i3 * 16 + l16]);
        M0 = __hmax2(M0, __hmax2(__hmax2(*(__half2*)&a.x, *(__half2*)&b.x),
                                 __hmax2(*(__half2*)&c.x, *(__half2*)&d.x)));
        M1 = __hmax2(M1, __hmax2(__hmax2(*(__half2*)&a.y, *(__half2*)&b.y),
                                 __hmax2(*(__half2*)&c.y, *(__half2*)&d.y)));
    }
    for (; p < e; p++) {
        int i0 = g_csr[p];
        uint2 a = __ldcg(&ubase[(size_t)i0 * 16 + l16]);
        M0 = __hmax2(M0, *(__half2*)&a.x);
        M1 = __hmax2(M1, *(__half2*)&a.y);
    }

    float2 f0 = __half22float2(M0);
    float2 f1 = __half22float2(M1);

    float px = pos[n * 3 + 0], py = pos[n * 3 + 1], pz = pos[n * 3 + 2];
    int k0 = 4 * l16;
    float4 hh = make_float4(0.f, 0.f, 0.f, 0.f);
    if (e > s) {
        hh.x = f0.x - (px * Wp[k0 + 0][0] + py * Wp[k0 + 0][1] + pz * Wp[k0 + 0][2]);
        hh.y = f0.y - (px * Wp[k0 + 1][0] + py * Wp[k0 + 1][1] + pz * Wp[k0 + 1][2]);
        hh.z = f1.x - (px * Wp[k0 + 2][0] + py * Wp[k0 + 2][1] + pz * Wp[k0 + 2][2]);
        hh.w = f1.y - (px * Wp[k0 + 3][0] + py * Wp[k0 + 3][1] + pz * Wp[k0 + 3][2]);
    }

    float sum = hh.x + hh.y + hh.z + hh.w;
    float sq  = hh.x * hh.x + hh.y * hh.y + hh.z * hh.z + hh.w * hh.w;
    #pragma unroll
    for (int o = 8; o > 0; o >>= 1) {
        sum += __shfl_xor_sync(0xffffffffu, sum, o);
        sq  += __shfl_xor_sync(0xffffffffu, sq, o);
    }
    float mean = sum * (1.0f / 64.0f);
    float var  = fmaxf(sq * (1.0f / 64.0f) - mean * mean, 0.f);
    float rstd = rsqrtf(var + 1e-5f);
    float4 o4;
    o4.x = fmaxf((hh.x - mean) * rstd * gs[k0 + 0] + bs[k0 + 0], 0.f);
    o4.y = fmaxf((hh.y - mean) * rstd * gs[k0 + 1] + bs[k0 + 1], 0.f);
    o4.z = fmaxf((hh.z - mean) * rstd * gs[k0 + 2] + bs[k0 + 2], 0.f);
    o4.w = fmaxf((hh.w - mean) * rstd * gs[k0 + 3] + bs[k0 + 3], 0.f);
    *(float4*)&g_z[(size_t)n * ZDIM + layer * 64 + k0] = o4;
}

// ---------------- MLP via HMMA, 32-node tile, fragment-ordered weights ----------------
#define OZH  0
#define OZL  20992
#define OH1H 41984
#define OH1L 50688
#define OH2H 59392
#define OH2L 68096
#define OH3  76800
#define OST  84992
#define SMEM_MLP 85248

__global__ __launch_bounds__(128) void k_mlp(const float* __restrict__ b1,
                                             const float* __restrict__ b2,
                                             const float* __restrict__ b3,
                                             const float* __restrict__ w4,
                                             const float* __restrict__ b4,
                                             const float* __restrict__ scale,
                                             float* __restrict__ out) {
    extern __shared__ char sm[];
    __half* zh  = (__half*)(sm + OZH);
    __half* zl  = (__half*)(sm + OZL);
    __half* h1h = (__half*)(sm + OH1H);
    __half* h1l = (__half*)(sm + OH1L);
    __half* h2h = (__half*)(sm + OH2H);
    __half* h2l = (__half*)(sm + OH2L);
    float*  h3s = (float*)(sm + OH3);
    float*  meansh = (float*)(sm + OST);
    float*  rstdsh = (float*)(sm + OST + 128);

    int tid = threadIdx.x;
    int n0 = blockIdx.x * 32;
    int warp = tid >> 5, lane = tid & 31;
    int g = lane >> 2, tq = lane & 3;

    {
        int node = warp * 8 + (lane >> 2), j = lane & 3;
        const float4* zr = (const float4*)&g_z[(size_t)(n0 + node) * ZDIM];
        float s = 0.f, sq = 0.f;
        for (int i = j; i < 80; i += 4) {
            float4 v = zr[i];
            s += v.x + v.y + v.z + v.w;
            sq += v.x * v.x + v.y * v.y + v.z * v.z + v.w * v.w;
        }
        s  += __shfl_down_sync(0xffffffffu, s, 2, 4);
        s  += __shfl_down_sync(0xffffffffu, s, 1, 4);
        sq += __shfl_down_sync(0xffffffffu, sq, 2, 4);
        sq += __shfl_down_sync(0xffffffffu, sq, 1, 4);
        if (j == 0) {
            float mean = s * (1.0f / 320.0f);
            float var  = fmaxf(sq * (1.0f / 320.0f) - mean * mean, 0.f);
            meansh[node] = mean;
            rstdsh[node] = rsqrtf(var + 1e-5f);
        }
    }
    __syncthreads();
    for (int i = tid; i < 32 * 320; i += 128) {
        int nn = i / 320, c = i - nn * 320;
        float v = (g_z[(size_t)(n0 + nn) * ZDIM + c] - meansh[nn]) * rstdsh[nn];
        __half h = __float2half(v);
        zh[nn * 328 + c] = h;
        zl[nn * 328 + c] = __float2half(v - __half2float(h));
    }
    __syncthreads();

    float d[2][4][4];

    // ---- layer 1: 320 -> 128 ----
    #pragma unroll
    for (int m = 0; m < 2; m++)
        #pragma unroll
        for (int t = 0; t < 4; t++) { d[m][t][0] = d[m][t][1] = d[m][t][2] = d[m][t][3] = 0.f; }
    for (int kt = 0; kt < 20; kt++) {
        int k0 = kt * 16;
        uint2 bh[4], bl[4];
        #pragma unroll
        for (int t = 0; t < 4; t++) {
            int fi = ((kt * 16 + warp * 4 + t) << 5) + lane;
            bh[t] = __ldg(&g_w1f_h[fi]);
            bl[t] = __ldg(&g_w1f_l[fi]);
        }
        #pragma unroll
        for (int m = 0; m < 2; m++) {
            int r0 = m * 16 + g, r1 = m * 16 + 8 + g;
            u32 ah0 = *(const u32*)&zh[r0 * 328 + k0 + tq * 2];
            u32 ah1 = *(const u32*)&zh[r1 * 328 + k0 + tq * 2];
            u32 ah2 = *(const u32*)&zh[r0 * 328 + k0 + 8 + tq * 2];
            u32 ah3 = *(const u32*)&zh[r1 * 328 + k0 + 8 + tq * 2];
            u32 al0 = *(const u32*)&zl[r0 * 328 + k0 + tq * 2];
            u32 al1 = *(const u32*)&zl[r1 * 328 + k0 + tq * 2];
            u32 al2 = *(const u32*)&zl[r0 * 328 + k0 + 8 + tq * 2];
            u32 al3 = *(const u32*)&zl[r1 * 328 + k0 + 8 + tq * 2];
            #pragma unroll
            for (int t = 0; t < 4; t++) {
                mma16816(d[m][t], ah0, ah1, ah2, ah3, bh[t].x, bh[t].y);
                mma16816(d[m][t], ah0, ah1, ah2, ah3, bl[t].x, bl[t].y);
                mma16816(d[m][t], al0, al1, al2, al3, bh[t].x, bh[t].y);
            }
        }
    }
    #pragma unroll
    for (int m = 0; m < 2; m++)
        #pragma unroll
        for (int t = 0; t < 4; t++) {
            int col = warp * 32 + t * 8 + tq * 2;
            float bb0 = b1[col], bb1 = b1[col + 1];
            int r0 = m * 16 + g, r1 = m * 16 + 8 + g;
            float v00 = fmaxf(d[m][t][0] + bb0, 0.f), v01 = fmaxf(d[m][t][1] + bb1, 0.f);
            float v10 = fmaxf(d[m][t][2] + bb0, 0.f), v11 = fmaxf(d[m][t][3] + bb1, 0.f);
            __half x;
            x = __float2half(v00); h1h[r0 * 136 + col] = x; h1l[r0 * 136 + col] = __float2half(v00 - __half2float(x));
            x = __float2half(v01); h1h[r0 * 136 + col + 1] = x; h1l[r0 * 136 + col + 1] = __float2half(v01 - __half2float(x));
            x = __float2half(v10); h1h[r1 * 136 + col] = x; h1l[r1 * 136 + col] = __float2half(v10 - __half2float(x));
            x = __float2half(v11); h1h[r1 * 136 + col + 1] = x; h1l[r1 * 136 + col + 1] = __float2half(v11 - __half2float(x));
        }
    __syncthreads();

    // ---- layer 2: 128 -> 128 ----
    #pragma unroll
    for (int m = 0; m < 2; m++)
        #pragma unroll
        for (int t = 0; t < 4; t++) { d[m][t][0] = d[m][t][1] = d[m][t][2] = d[m][t][3] = 0.f; }
    for (int kt = 0; kt < 8; kt++) {
        int k0 = kt * 16;
        uint2 bh[4], bl[4];
        #pragma unroll
        for (int t = 0; t < 4; t++) {
            int fi = ((kt * 16 + warp * 4 + t) << 5) + lane;
            bh[t] = __ldg(&g_w2f_h[fi]);
            bl[t] = __ldg(&g_w2f_l[fi]);
        }
        #pragma unroll
        for (int m = 0; m < 2; m++) {
            int r0 = m * 16 + g, r1 = m * 16 + 8 + g;
            u32 ah0 = *(const u32*)&h1h[r0 * 136 + k0 + tq * 2];
            u32 ah1 = *(const u32*)&h1h[r1 * 136 + k0 + tq * 2];
            u32 ah2 = *(const u32*)&h1h[r0 * 136 + k0 + 8 + tq * 2];
            u32 ah3 = *(const u32*)&h1h[r1 * 136 + k0 + 8 + tq * 2];
            u32 al0 = *(const u32*)&h1l[r0 * 136 + k0 + tq * 2];
            u32 al1 = *(const u32*)&h1l[r1 * 136 + k0 + tq * 2];
            u32 al2 = *(const u32*)&h1l[r0 * 136 + k0 + 8 + tq * 2];
            u32 al3 = *(const u32*)&h1l[r1 * 136 + k0 + 8 + tq * 2];
            #pragma unroll
            for (int t = 0; t < 4; t++) {
                mma16816(d[m][t], ah0, ah1, ah2, ah3, bh[t].x, bh[t].y);
                mma16816(d[m][t], ah0, ah1, ah2, ah3, bl[t].x, bl[t].y);
                mma16816(d[m][t], al0, al1, al2, al3, bh[t].x, bh[t].y);
            }
        }
    }
    #pragma unroll
    for (int m = 0; m < 2; m++)
        #pragma unroll
        for (int t = 0; t < 4; t++) {
            int col = warp * 32 + t * 8 + tq * 2;
            float bb0 = b2[col], bb1 = b2[col + 1];
            int r0 = m * 16 + g, r1 = m * 16 + 8 + g;
            float v00 = fmaxf(d[m][t][0] + bb0, 0.f), v01 = fmaxf(d[m][t][1] + bb1, 0.f);
            float v10 = fmaxf(d[m][t][2] + bb0, 0.f), v11 = fmaxf(d[m][t][3] + bb1, 0.f);
            __half x;
            x = __float2half(v00); h2h[r0 * 136 + col] = x; h2l[r0 * 136 + col] = __float2half(v00 - __half2float(x));
            x = __float2half(v01); h2h[r0 * 136 + col + 1] = x; h2l[r0 * 136 + col + 1] = __float2half(v01 - __half2float(x));
            x = __float2half(v10); h2h[r1 * 136 + col] = x; h2l[r1 * 136 + col] = __float2half(v10 - __half2float(x));
            x = __float2half(v11); h2h[r1 * 136 + col + 1] = x; h2l[r1 * 136 + col + 1] = __float2half(v11 - __half2float(x));
        }
    __syncthreads();

    // ---- layer 3: 128 -> 64 ----
    #pragma unroll
    for (int m = 0; m < 2; m++)
        #pragma unroll
        for (int t = 0; t < 2; t++) { d[m][t][0] = d[m][t][1] = d[m][t][2] = d[m][t][3] = 0.f; }
    for (int kt = 0; kt < 8; kt++) {
        int k0 = kt * 16;
        uint2 bh[2], bl[2];
        #pragma unroll
        for (int t = 0; t < 2; t++) {
            int fi = ((kt * 8 + warp * 2 + t) << 5) + lane;
            bh[t] = __ldg(&g_w3f_h[fi]);
            bl[t] = __ldg(&g_w3f_l[fi]);
        }
        #pragma unroll
        for (int m = 0; m < 2; m++) {
            int r0 = m * 16 + g, r1 = m * 16 + 8 + g;
            u32 ah0 = *(const u32*)&h2h[r0 * 136 + k0 + tq * 2];
            u32 ah1 = *(const u32*)&h2h[r1 * 136 + k0 + tq * 2];
            u32 ah2 = *(const u32*)&h2h[r0 * 136 + k0 + 8 + tq * 2];
            u32 ah3 = *(const u32*)&h2h[r1 * 136 + k0 + 8 + tq * 2];
            u32 al0 = *(const u32*)&h2l[r0 * 136 + k0 + tq * 2];
            u32 al1 = *(const u32*)&h2l[r1 * 136 + k0 + tq * 2];
            u32 al2 = *(const u32*)&h2l[r0 * 136 + k0 + 8 + tq * 2];
            u32 al3 = *(const u32*)&h2l[r1 * 136 + k0 + 8 + tq * 2];
            #pragma unroll
            for (int t = 0; t < 2; t++) {
                mma16816(d[m][t], ah0, ah1, ah2, ah3, bh[t].x, bh[t].y);
                mma16816(d[m][t], ah0, ah1, ah2, ah3, bl[t].x, bl[t].y);
                mma16816(d[m][t], al0, al1, al2, al3, bh[t].x, bh[t].y);
            }
        }
    }
    #pragma unroll
    for (int m = 0; m < 2; m++)
        #pragma unroll
        for (int t = 0; t < 2; t++) {
            int col = warp * 16 + t * 8 + tq * 2;
            float bb0 = b3[col], bb1 = b3[col + 1];
            int r0 = m * 16 + g, r1 = m * 16 + 8 + g;
            h3s[r0 * 64 + col]     = fmaxf(d[m][t][0] + bb0, 0.f);
            h3s[r0 * 64 + col + 1] = fmaxf(d[m][t][1] + bb1, 0.f);
            h3s[r1 * 64 + col]     = fmaxf(d[m][t][2] + bb0, 0.f);
            h3s[r1 * 64 + col + 1] = fmaxf(d[m][t][3] + bb1, 0.f);
        }
    __syncthreads();

    // ---- layer 4: 64 -> 2, * scale ----
    if (tid < 64) {
        int nn = tid >> 1, o = tid & 1;
        int n = n0 + nn;
        if (n < N_NODES) {
            float a = b4[o];
            const float* wrow = &w4[o * 64];
            #pragma unroll 8
            for (int c = 0; c < 64; c++) a += h3s[nn * 64 + c] * wrow[c];
            out[(size_t)n * 2 + o] = a * scale[o];
        }
    }
}

// ---------------- launch ----------------
extern "C" void kernel_launch(void* const* d_in, const int* in_sizes, int n_in,
                              void* d_out, int out_size) {
    const float* x     = (const float*)d_in[0];
    const float* pos   = (const float*)d_in[1];
    const int*   ei    = (const int*)d_in[2];
    const float* W0    = (const float*)d_in[3];
    const float* Ws    = (const float*)d_in[4];
    const float* ln_g  = (const float*)d_in[5];
    const float* ln_b  = (const float*)d_in[6];
    const float* w1    = (const float*)d_in[7];
    const float* b1    = (const float*)d_in[8];
    const float* w2    = (const float*)d_in[9];
    const float* b2    = (const float*)d_in[10];
    const float* w3    = (const float*)d_in[11];
    const float* b3    = (const float*)d_in[12];
    const float* w4    = (const float*)d_in[13];
    const float* b4    = (const float*)d_in[14];
    const float* scale = (const float*)d_in[15];
    float* out = (float*)d_out;

    cudaFuncSetAttribute(k_mlp, cudaFuncAttributeMaxDynamicSharedMemorySize, SMEM_MLP);

    const int TGRID = (N_NODES + 31) / 32;  // 1563

    k_prep<<<3194, 256>>>(ei, W0, Ws, w1, w2, w3);                 // #1 (hist + quant + frags)
    k_scan_local<<<SCAN_BLK, 512>>>();                             // #2
    k_scan_add<<<SCAN_BLK, 512>>>();                               // #3
    k_transform0<<<TGRID, 256>>>(x, pos);                          // #4  <- profiled
    k_scatter<<<(N_EDGES + 255) / 256, 256>>>(ei);                 // #5 (+ degree hist)
    k_dscan<<<1, 128>>>();                                         // #6
    k_dperm<<<(N_NODES + 255) / 256, 256>>>();                     // #7
    k_aggregate<<<N_NODES / 16, 256>>>(pos, ln_g, ln_b, 0, 4);     // #8

    for (int i = 1; i < 5; i++) {
        k_transform<<<TGRID, 256>>>(pos, i);
        k_aggregate<<<N_NODES / 16, 256>>>(pos, ln_g, ln_b, i, 67);
    }

    k_mlp<<<TGRID, 128, SMEM_MLP>>>(b1, b2, b3, w4, b4, scale, out);
}

// round 16
// speedup vs baseline: 1.0702x; 1.0702x over previous
#include <cuda_runtime.h>
#include <cuda_bf16.h>
#include <cuda_fp16.h>
#include <cfloat>
#include <cstdint>

#define N_NODES 50000
#define N_EDGES 800000
#define HID 64
#define ZDIM 320
#define WSTRIDE 68                 // padded W row (64x68, zeros in pad)
#define WSZ (64 * WSTRIDE)
#define SCAN_BLK 98                // ceil(50000/512)
#define NPADZ 50016                // pad g_z rows for 32-node MLP tiles

typedef unsigned long long ull;
typedef uint32_t u32;

// ---------------- device scratch ----------------
__device__ __half g_uh[N_NODES * HID];     // u stored fp16 (gather payload)
__device__ float g_z[NPADZ * ZDIM];        // pad rows never written -> zero
__device__ int   g_cnt[N_NODES];           // INVARIANT: all-zero at kernel_launch entry
__device__ int   g_off[N_NODES + 1];
__device__ int   g_cur[N_NODES];
__device__ int   g_csr[N_EDGES];
__device__ int   g_bsum[SCAN_BLK];
__device__ float g_Wq[5 * WSZ];            // all 5 quantized layer weights
// HMMA fragment-ordered weights (hi/lo fp16 split):
__device__ uint2 g_w1f_h[20 * 16 * 32], g_w1f_l[20 * 16 * 32];   // 320->128
__device__ uint2 g_w2f_h[8 * 16 * 32],  g_w2f_l[8 * 16 * 32];    // 128->128
__device__ uint2 g_w3f_h[8 * 8 * 32],   g_w3f_l[8 * 8 * 32];     // 128->64

// ---------------- f32x2 helpers ----------------
__device__ __forceinline__ ull fma2(ull a, ull b, ull c) {
    ull d;
    asm("fma.rn.f32x2 %0, %1, %2, %3;" : "=l"(d) : "l"(a), "l"(b), "l"(c));
    return d;
}
__device__ __forceinline__ float sum2(ull a) {
    float lo, hi;
    asm("mov.b64 {%0, %1}, %2;" : "=f"(lo), "=f"(hi) : "l"(a));
    return lo + hi;
}

// ---------------- mma.sync m16n8k16 f16 helper ----------------
__device__ __forceinline__ void mma16816(float* d, u32 a0, u32 a1, u32 a2, u32 a3,
                                         u32 b0, u32 b1) {
    asm volatile(
        "mma.sync.aligned.m16n8k16.row.col.f32.f16.f16.f32 "
        "{%0,%1,%2,%3}, {%4,%5,%6,%7}, {%8,%9}, {%0,%1,%2,%3};"
        : "+f"(d[0]), "+f"(d[1]), "+f"(d[2]), "+f"(d[3])
        : "r"(a0), "r"(a1), "r"(a2), "r"(a3), "r"(b0), "r"(b1));
}

__device__ __forceinline__ u32 packh2(float a, float b) {
    __half2 h = __floats2half2_rn(a, b);
    return *(u32*)&h;
}

// ---------------- CSR construction ----------------
__global__ void k_hist(const int* __restrict__ ei) {
    int e = blockIdx.x * blockDim.x + threadIdx.x;
    if (e < N_EDGES) atomicAdd(&g_cnt[ei[N_EDGES + e]], 1);
}

__global__ void k_scan_local() {
    __shared__ int wsums[16];
    int b = blockIdx.x, tid = threadIdx.x, lane = tid & 31, wid = tid >> 5;
    int i = b * 512 + tid;
    int v = (i < N_NODES) ? g_cnt[i] : 0;
    int x = v;
    #pragma unroll
    for (int o = 1; o < 32; o <<= 1) {
        int y = __shfl_up_sync(0xffffffffu, x, o);
        if (lane >= o) x += y;
    }
    if (lane == 31) wsums[wid] = x;
    __syncthreads();
    if (wid == 0 && lane < 16) {
        int w = wsums[lane];
        int xs = w;
        #pragma unroll
        for (int o = 1; o < 16; o <<= 1) {
            int y = __shfl_up_sync(0xffffu, xs, o);
            if (lane >= o) xs += y;
        }
        wsums[lane] = xs - w;
    }
    __syncthreads();
    int excl = x - v + wsums[wid];
    if (i < N_NODES) g_off[i] = excl;
    if (tid == 511) g_bsum[b] = excl + v;
}

__global__ void k_scan_add() {
    __shared__ int part[4];
    int b = blockIdx.x, tid = threadIdx.x, lane = tid & 31, wid = tid >> 5;
    int v = 0;
    if (tid < b) v = g_bsum[tid];      // b <= 97 < 128
    if (tid < 128) {
        #pragma unroll
        for (int o = 16; o > 0; o >>= 1) v += __shfl_xor_sync(0xffffffffu, v, o);
        if (lane == 0) part[wid] = v;
    }
    __syncthreads();
    int add = part[0] + part[1] + part[2] + part[3];
    int i = b * 512 + tid;
    if (i < N_NODES) {
        int o = g_off[i] + add;
        g_off[i] = o;
        g_cur[i] = o;
        g_cnt[i] = 0;   // restore zero-invariant for next replay
    }
    if (i == 0) g_off[N_NODES] = N_EDGES;
}

__global__ void k_scatter(const int* __restrict__ ei) {
    int e = blockIdx.x * blockDim.x + threadIdx.x;
    if (e < N_EDGES) {
        int d = ei[N_EDGES + e];
        int p = atomicAdd(&g_cur[d], 1);
        g_csr[p] = ei[e];
    }
}

// ---------------- weight prep (fake-quant + HMMA fragment layout) ----------------
__global__ void k_quant_prep(const float* __restrict__ W0, const float* __restrict__ Ws,
                             const float* __restrict__ w1, const float* __restrict__ w2,
                             const float* __restrict__ w3) {
    int b = blockIdx.x, tid = threadIdx.x;
    if (b < 5) {
        __shared__ float red[256];
        const float* W = (b == 0) ? W0 : (Ws + (size_t)(b - 1) * 64 * 67);
        int cols = (b == 0) ? 4 : 67;
        int n = 64 * cols;
        float* dst = g_Wq + b * WSZ;

        float m = 0.f;
        for (int i = tid; i < n; i += 256) m = fmaxf(m, fabsf(W[i]));
        red[tid] = m;
        __syncthreads();
        for (int s = 128; s > 0; s >>= 1) {
            if (tid < s) red[tid] = fmaxf(red[tid], red[tid + s]);
            __syncthreads();
        }
        float sc = fmaxf(red[0] * (1.0f / 127.0f), 1e-8f);
        for (int i = tid; i < WSZ; i += 256) dst[i] = 0.0f;
        __syncthreads();
        for (int i = tid; i < n; i += 256) {
            int k = i / cols, c = i % cols;
            float q = rintf(W[i] / sc);
            q = fminf(fmaxf(q, -127.0f), 127.0f) * sc;
            dst[k * WSTRIDE + c] = q;
        }
        return;
    }
    int idx = (b - 5) * 256 + tid;
    const float* src;
    uint2 *dh, *dl;
    int K, slot;
    if (idx < 10240)      { src = w1; dh = g_w1f_h; dl = g_w1f_l; K = 320; slot = idx;
                            int kt = slot >> 9, rem = slot & 511, nb = rem >> 5, lane = rem & 31;
                            int g = lane >> 2, tq = lane & 3;
                            int n = nb * 8 + g, kb = kt * 16 + tq * 2;
                            float v0 = src[n * K + kb],     v1 = src[n * K + kb + 1];
                            float v2 = src[n * K + kb + 8], v3 = src[n * K + kb + 9];
                            __half h0 = __float2half(v0), h1 = __float2half(v1);
                            __half h2 = __float2half(v2), h3 = __float2half(v3);
                            dh[slot] = make_uint2(packh2(__half2float(h0), __half2float(h1)),
                                                  packh2(__half2float(h2), __half2float(h3)));
                            dl[slot] = make_uint2(packh2(v0 - __half2float(h0), v1 - __half2float(h1)),
                                                  packh2(v2 - __half2float(h2), v3 - __half2float(h3)));
    } else if (idx < 14336) { src = w2; dh = g_w2f_h; dl = g_w2f_l; K = 128; slot = idx - 10240;
                            int kt = slot >> 9, rem = slot & 511, nb = rem >> 5, lane = rem & 31;
                            int g = lane >> 2, tq = lane & 3;
                            int n = nb * 8 + g, kb = kt * 16 + tq * 2;
                            float v0 = src[n * K + kb],     v1 = src[n * K + kb + 1];
                            float v2 = src[n * K + kb + 8], v3 = src[n * K + kb + 9];
                            __half h0 = __float2half(v0), h1 = __float2half(v1);
                            __half h2 = __float2half(v2), h3 = __float2half(v3);
                            dh[slot] = make_uint2(packh2(__half2float(h0), __half2float(h1)),
                                                  packh2(__half2float(h2), __half2float(h3)));
                            dl[slot] = make_uint2(packh2(v0 - __half2float(h0), v1 - __half2float(h1)),
                                                  packh2(v2 - __half2float(h2), v3 - __half2float(h3)));
    } else if (idx < 16384) { src = w3; dh = g_w3f_h; dl = g_w3f_l; K = 128; slot = idx - 14336;
                            int kt = slot >> 8, rem = slot & 255, nb = rem >> 5, lane = rem & 31;
                            int g = lane >> 2, tq = lane & 3;
                            int n = nb * 8 + g, kb = kt * 16 + tq * 2;
                            float v0 = src[n * K + kb],     v1 = src[n * K + kb + 1];
                            float v2 = src[n * K + kb + 8], v3 = src[n * K + kb + 9];
                            __half h0 = __float2half(v0), h1 = __float2half(v1);
                            __half h2 = __float2half(v2), h3 = __float2half(v3);
                            dh[slot] = make_uint2(packh2(__half2float(h0), __half2float(h1)),
                                                  packh2(__half2float(h2), __half2float(h3)));
                            dl[slot] = make_uint2(packh2(v0 - __half2float(h0), v1 - __half2float(h1)),
                                                  packh2(v2 - __half2float(h2), v3 - __half2float(h3)));
    }
}

// ---------------- layer-0 transform ----------------
__global__ __launch_bounds__(256) void k_transform0(const float* __restrict__ x,
                                                    const float* __restrict__ pos) {
    __shared__ float4 Wsh[64];
    __shared__ float  xs[32];
    __shared__ float  ps[96];
    int tid = threadIdx.x;
    int nbase = blockIdx.x * 32;
    if (tid < 64) {
        const float* wr = g_Wq + tid * WSTRIDE;
        Wsh[tid] = make_float4(wr[0], wr[1], wr[2], wr[3]);
    } else if (tid < 96) {
        int n = nbase + (tid - 64);
        xs[tid - 64] = (n < N_NODES) ? x[n] : 0.f;
    } else if (tid < 192) {
        int j = tid - 96;
        int gi = nbase * 3 + j;
        ps[j] = (gi < N_NODES * 3) ? pos[gi] : 0.f;
    }
    __syncthreads();
    int k = tid & 63, grp = tid >> 6;
    float4 w = Wsh[k];
    #pragma unroll
    for (int j = 0; j < 8; j++) {
        int nn = grp * 8 + j;
        int n = nbase + nn;
        if (n < N_NODES) {
            float r = w.x * xs[nn] + w.y * ps[3 * nn] + w.z * ps[3 * nn + 1] + w.w * ps[3 * nn + 2];
            g_uh[(size_t)n * HID + k] = __float2half(r);
        }
    }
}

// ---------------- layers 1-4 transform ----------------
__global__ __launch_bounds__(256) void k_transform(const float* __restrict__ pos, int layer) {
    constexpr int C4 = 17;
    __shared__ float Wsh[WSZ];
    __shared__ float fsh[32][WSTRIDE];
    int tid = threadIdx.x;
    int k = tid & 63, grp = tid >> 6;
    const float* Wsrc = g_Wq + layer * WSZ;
    {
        const float4* s4 = (const float4*)Wsrc;
        float4* d4 = (float4*)Wsh;
        #pragma unroll
        for (int i = tid; i < WSZ / 4; i += 256) d4[i] = s4[i];
    }
    int nbase = blockIdx.x * 32;
    const float* h = g_z + (size_t)(layer - 1) * HID;
    #pragma unroll
    for (int i = tid; i < 32 * 64; i += 256) {
        int nn = i >> 6, c = i & 63;
        int gn = nbase + nn;
        fsh[nn][c] = (gn < N_NODES) ? h[(size_t)gn * ZDIM + c] : 0.f;
    }
    if (tid < 128) {
        int nn = tid >> 2, j = tid & 3;
        int gn = nbase + nn;
        float v = 0.f;
        if (j < 3 && gn < N_NODES) v = pos[gn * 3 + j];
        fsh[nn][64 + j] = v;
    }
    __syncthreads();
    ull w2r[C4 * 2];
    #pragma unroll
    for (int c4 = 0; c4 < C4; c4++) {
        ulonglong2 wv = *(const ulonglong2*)&Wsh[k * WSTRIDE + 4 * c4];
        w2r[2 * c4] = wv.x; w2r[2 * c4 + 1] = wv.y;
    }
    ull acc[8];
    #pragma unroll
    for (int j = 0; j < 8; j++) acc[j] = 0;
    #pragma unroll
    for (int c4 = 0; c4 < C4; c4++) {
        ull w01 = w2r[2 * c4], w23 = w2r[2 * c4 + 1];
        #pragma unroll
        for (int j = 0; j < 8; j++) {
            ulonglong2 f = *(const ulonglong2*)&fsh[grp * 8 + j][4 * c4];
            acc[j] = fma2(f.x, w01, acc[j]);
            acc[j] = fma2(f.y, w23, acc[j]);
        }
    }
    #pragma unroll
    for (int j = 0; j < 8; j++) {
        int n = nbase + grp * 8 + j;
        if (n < N_NODES) g_uh[(size_t)n * HID + k] = __float2half(sum2(acc[j]));
    }
}

// ---------------- aggregation: 2 nodes/warp, 16 lanes x half2x2 (8B/lane) ----------------
__global__ __launch_bounds__(256) void k_aggregate(const float* __restrict__ pos,
                                                   const float* __restrict__ ln_g,
                                                   const float* __restrict__ ln_b,
                                                   int layer, int cols) {
    __shared__ float Wp[64][3];
    __shared__ float gs[64], bs[64];
    int tid = threadIdx.x;
    if (tid < 64) { gs[tid] = ln_g[layer * 64 + tid]; bs[tid] = ln_b[layer * 64 + tid]; }
    const float* Wsrc = g_Wq + layer * WSZ;
    for (int i = tid; i < 192; i += 256) {
        int k = i / 3, j = i % 3;
        Wp[k][j] = Wsrc[k * WSTRIDE + (cols - 3) + j];
    }
    __syncthreads();

    int wid = tid >> 5, lane = tid & 31;
    int half = lane >> 4, l16 = lane & 15;
    int n = blockIdx.x * 16 + wid * 2 + half;
    int s = g_off[n], e = g_off[n + 1];
    const uint2* ubase = (const uint2*)g_uh;

    __half2 M0 = __float2half2_rn(-65504.f);
    __half2 M1 = __float2half2_rn(-65504.f);
    int p = s;
    for (; p + 8 <= e; p += 8) {
        int i0 = g_csr[p],     i1 = g_csr[p + 1], i2 = g_csr[p + 2], i3 = g_csr[p + 3];
        int i4 = g_csr[p + 4], i5 = g_csr[p + 5], i6 = g_csr[p + 6], i7 = g_csr[p + 7];
        uint2 a = __ldcg(&ubase[(size_t)i0 * 16 + l16]);
        uint2 b = __ldcg(&ubase[(size_t)i1 * 16 + l16]);
        uint2 c = __ldcg(&ubase[(size_t)i2 * 16 + l16]);
        uint2 d = __ldcg(&ubase[(size_t)i3 * 16 + l16]);
        uint2 f = __ldcg(&ubase[(size_t)i4 * 16 + l16]);
        uint2 g = __ldcg(&ubase[(size_t)i5 * 16 + l16]);
        uint2 h = __ldcg(&ubase[(size_t)i6 * 16 + l16]);
        uint2 q = __ldcg(&ubase[(size_t)i7 * 16 + l16]);
        M0 = __hmax2(M0, __hmax2(__hmax2(*(__half2*)&a.x, *(__half2*)&b.x),
                                 __hmax2(*(__half2*)&c.x, *(__half2*)&d.x)));
        M0 = __hmax2(M0, __hmax2(__hmax2(*(__half2*)&f.x, *(__half2*)&g.x),
                                 __hmax2(*(__half2*)&h.x, *(__half2*)&q.x)));
        M1 = __hmax2(M1, __hmax2(__hmax2(*(__half2*)&a.y, *(__half2*)&b.y),
                                 __hmax2(*(__half2*)&c.y, *(__half2*)&d.y)));
        M1 = __hmax2(M1, __hmax2(__hmax2(*(__half2*)&f.y, *(__half2*)&g.y),
                                 __hmax2(*(__half2*)&h.y, *(__half2*)&q.y)));
    }
    for (; p + 4 <= e; p += 4) {
        int i0 = g_csr[p], i1 = g_csr[p + 1], i2 = g_csr[p + 2], i3 = g_csr[p + 3];
        uint2 a = __ldcg(&ubase[(size_t)i0 * 16 + l16]);
        uint2 b = __ldcg(&ubase[(size_t)i1 * 16 + l16]);
        uint2 c = __ldcg(&ubase[(size_t)i2 * 16 + l16]);
        uint2 d = __ldcg(&ubase[(size_t)i3 * 16 + l16]);
        M0 = __hmax2(M0, __hmax2(__hmax2(*(__half2*)&a.x, *(__half2*)&b.x),
                                 __hmax2(*(__half2*)&c.x, *(__half2*)&d.x)));
        M1 = __hmax2(M1, __hmax2(__hmax2(*(__half2*)&a.y, *(__half2*)&b.y),
                                 __hmax2(*(__half2*)&c.y, *(__half2*)&d.y)));
    }
    for (; p < e; p++) {
        int i0 = g_csr[p];
        uint2 a = __ldcg(&ubase[(size_t)i0 * 16 + l16]);
        M0 = __hmax2(M0, *(__half2*)&a.x);
        M1 = __hmax2(M1, *(__half2*)&a.y);
    }

    float2 f0 = __half22float2(M0);
    float2 f1 = __half22float2(M1);

    float px = pos[n * 3 + 0], py = pos[n * 3 + 1], pz = pos[n * 3 + 2];
    int k0 = 4 * l16;
    float4 hh = make_float4(0.f, 0.f, 0.f, 0.f);
    if (e > s) {
        hh.x = f0.x - (px * Wp[k0 + 0][0] + py * Wp[k0 + 0][1] + pz * Wp[k0 + 0][2]);
        hh.y = f0.y - (px * Wp[k0 + 1][0] + py * Wp[k0 + 1][1] + pz * Wp[k0 + 1][2]);
        hh.z = f1.x - (px * Wp[k0 + 2][0] + py * Wp[k0 + 2][1] + pz * Wp[k0 + 2][2]);
        hh.w = f1.y - (px * Wp[k0 + 3][0] + py * Wp[k0 + 3][1] + pz * Wp[k0 + 3][2]);
    }

    float sum = hh.x + hh.y + hh.z + hh.w;
    float sq  = hh.x * hh.x + hh.y * hh.y + hh.z * hh.z + hh.w * hh.w;
    #pragma unroll
    for (int o = 8; o > 0; o >>= 1) {
        sum += __shfl_xor_sync(0xffffffffu, sum, o);
        sq  += __shfl_xor_sync(0xffffffffu, sq, o);
    }
    float mean = sum * (1.0f / 64.0f);
    float var  = fmaxf(sq * (1.0f / 64.0f) - mean * mean, 0.f);
    float rstd = rsqrtf(var + 1e-5f);
    float4 o4;
    o4.x = fmaxf((hh.x - mean) * rstd * gs[k0 + 0] + bs[k0 + 0], 0.f);
    o4.y = fmaxf((hh.y - mean) * rstd * gs[k0 + 1] + bs[k0 + 1], 0.f);
    o4.z = fmaxf((hh.z - mean) * rstd * gs[k0 + 2] + bs[k0 + 2], 0.f);
    o4.w = fmaxf((hh.w - mean) * rstd * gs[k0 + 3] + bs[k0 + 3], 0.f);
    *(float4*)&g_z[(size_t)n * ZDIM + layer * 64 + k0] = o4;
}

// ---------------- MLP via HMMA, 32-node tile, fragment-ordered weights ----------------
#define OZH  0
#define OZL  20992
#define OH1H 41984
#define OH1L 50688
#define OH2H 59392
#define OH2L 68096
#define OH3  76800
#define OST  84992
#define SMEM_MLP 85248

__global__ __launch_bounds__(128) void k_mlp(const float* __restrict__ b1,
                                             const float* __restrict__ b2,
                                             const float* __restrict__ b3,
                                             const float* __restrict__ w4,
                                             const float* __restrict__ b4,
                                             const float* __restrict__ scale,
                                             float* __restrict__ out) {
    extern __shared__ char sm[];
    __half* zh  = (__half*)(sm + OZH);
    __half* zl  = (__half*)(sm + OZL);
    __half* h1h = (__half*)(sm + OH1H);
    __half* h1l = (__half*)(sm + OH1L);
    __half* h2h = (__half*)(sm + OH2H);
    __half* h2l = (__half*)(sm + OH2L);
    float*  h3s = (float*)(sm + OH3);
    float*  meansh = (float*)(sm + OST);
    float*  rstdsh = (float*)(sm + OST + 128);

    int tid = threadIdx.x;
    int n0 = blockIdx.x * 32;
    int warp = tid >> 5, lane = tid & 31;
    int g = lane >> 2, tq = lane & 3;

    {
        int node = warp * 8 + (lane >> 2), j = lane & 3;
        const float4* zr = (const float4*)&g_z[(size_t)(n0 + node) * ZDIM];
        float s = 0.f, sq = 0.f;
        for (int i = j; i < 80; i += 4) {
            float4 v = zr[i];
            s += v.x + v.y + v.z + v.w;
            sq += v.x * v.x + v.y * v.y + v.z * v.z + v.w * v.w;
        }
        s  += __shfl_down_sync(0xffffffffu, s, 2, 4);
        s  += __shfl_down_sync(0xffffffffu, s, 1, 4);
        sq += __shfl_down_sync(0xffffffffu, sq, 2, 4);
        sq += __shfl_down_sync(0xffffffffu, sq, 1, 4);
        if (j == 0) {
            float mean = s * (1.0f / 320.0f);
            float var  = fmaxf(sq * (1.0f / 320.0f) - mean * mean, 0.f);
            meansh[node] = mean;
            rstdsh[node] = rsqrtf(var + 1e-5f);
        }
    }
    __syncthreads();
    for (int i = tid; i < 32 * 320; i += 128) {
        int nn = i / 320, c = i - nn * 320;
        float v = (g_z[(size_t)(n0 + nn) * ZDIM + c] - meansh[nn]) * rstdsh[nn];
        __half h = __float2half(v);
        zh[nn * 328 + c] = h;
        zl[nn * 328 + c] = __float2half(v - __half2float(h));
    }
    __syncthreads();

    float d[2][4][4];

    // ---- layer 1: 320 -> 128 ----
    #pragma unroll
    for (int m = 0; m < 2; m++)
        #pragma unroll
        for (int t = 0; t < 4; t++) { d[m][t][0] = d[m][t][1] = d[m][t][2] = d[m][t][3] = 0.f; }
    for (int kt = 0; kt < 20; kt++) {
        int k0 = kt * 16;
        uint2 bh[4], bl[4];
        #pragma unroll
        for (int t = 0; t < 4; t++) {
            int fi = ((kt * 16 + warp * 4 + t) << 5) + lane;
            bh[t] = __ldg(&g_w1f_h[fi]);
            bl[t] = __ldg(&g_w1f_l[fi]);
        }
        #pragma unroll
        for (int m = 0; m < 2; m++) {
            int r0 = m * 16 + g, r1 = m * 16 + 8 + g;
            u32 ah0 = *(const u32*)&zh[r0 * 328 + k0 + tq * 2];
            u32 ah1 = *(const u32*)&zh[r1 * 328 + k0 + tq * 2];
            u32 ah2 = *(const u32*)&zh[r0 * 328 + k0 + 8 + tq * 2];
            u32 ah3 = *(const u32*)&zh[r1 * 328 + k0 + 8 + tq * 2];
            u32 al0 = *(const u32*)&zl[r0 * 328 + k0 + tq * 2];
            u32 al1 = *(const u32*)&zl[r1 * 328 + k0 + tq * 2];
            u32 al2 = *(const u32*)&zl[r0 * 328 + k0 + 8 + tq * 2];
            u32 al3 = *(const u32*)&zl[r1 * 328 + k0 + 8 + tq * 2];
            #pragma unroll
            for (int t = 0; t < 4; t++) {
                mma16816(d[m][t], ah0, ah1, ah2, ah3, bh[t].x, bh[t].y);
                mma16816(d[m][t], ah0, ah1, ah2, ah3, bl[t].x, bl[t].y);
                mma16816(d[m][t], al0, al1, al2, al3, bh[t].x, bh[t].y);
            }
        }
    }
    #pragma unroll
    for (int m = 0; m < 2; m++)
        #pragma unroll
        for (int t = 0; t < 4; t++) {
            int col = warp * 32 + t * 8 + tq * 2;
            float bb0 = b1[col], bb1 = b1[col + 1];
            int r0 = m * 16 + g, r1 = m * 16 + 8 + g;
            float v00 = fmaxf(d[m][t][0] + bb0, 0.f), v01 = fmaxf(d[m][t][1] + bb1, 0.f);
            float v10 = fmaxf(d[m][t][2] + bb0, 0.f), v11 = fmaxf(d[m][t][3] + bb1, 0.f);
            __half x;
            x = __float2half(v00); h1h[r0 * 136 + col] = x; h1l[r0 * 136 + col] = __float2half(v00 - __half2float(x));
            x = __float2half(v01); h1h[r0 * 136 + col + 1] = x; h1l[r0 * 136 + col + 1] = __float2half(v01 - __half2float(x));
            x = __float2half(v10); h1h[r1 * 136 + col] = x; h1l[r1 * 136 + col] = __float2half(v10 - __half2float(x));
            x = __float2half(v11); h1h[r1 * 136 + col + 1] = x; h1l[r1 * 136 + col + 1] = __float2half(v11 - __half2float(x));
        }
    __syncthreads();

    // ---- layer 2: 128 -> 128 ----
    #pragma unroll
    for (int m = 0; m < 2; m++)
        #pragma unroll
        for (int t = 0; t < 4; t++) { d[m][t][0] = d[m][t][1] = d[m][t][2] = d[m][t][3] = 0.f; }
    for (int kt = 0; kt < 8; kt++) {
        int k0 = kt * 16;
        uint2 bh[4], bl[4];
        #pragma unroll
        for (int t = 0; t < 4; t++) {
            int fi = ((kt * 16 + warp * 4 + t) << 5) + lane;
            bh[t] = __ldg(&g_w2f_h[fi]);
            bl[t] = __ldg(&g_w2f_l[fi]);
        }
        #pragma unroll
        for (int m = 0; m < 2; m++) {
            int r0 = m * 16 + g, r1 = m * 16 + 8 + g;
            u32 ah0 = *(const u32*)&h1h[r0 * 136 + k0 + tq * 2];
            u32 ah1 = *(const u32*)&h1h[r1 * 136 + k0 + tq * 2];
            u32 ah2 = *(const u32*)&h1h[r0 * 136 + k0 + 8 + tq * 2];
            u32 ah3 = *(const u32*)&h1h[r1 * 136 + k0 + 8 + tq * 2];
            u32 al0 = *(const u32*)&h1l[r0 * 136 + k0 + tq * 2];
            u32 al1 = *(const u32*)&h1l[r1 * 136 + k0 + tq * 2];
            u32 al2 = *(const u32*)&h1l[r0 * 136 + k0 + 8 + tq * 2];
            u32 al3 = *(const u32*)&h1l[r1 * 136 + k0 + 8 + tq * 2];
            #pragma unroll
            for (int t = 0; t < 4; t++) {
                mma16816(d[m][t], ah0, ah1, ah2, ah3, bh[t].x, bh[t].y);
                mma16816(d[m][t], ah0, ah1, ah2, ah3, bl[t].x, bl[t].y);
                mma16816(d[m][t], al0, al1, al2, al3, bh[t].x, bh[t].y);
            }
        }
    }
    #pragma unroll
    for (int m = 0; m < 2; m++)
        #pragma unroll
        for (int t = 0; t < 4; t++) {
            int col = warp * 32 + t * 8 + tq * 2;
            float bb0 = b2[col], bb1 = b2[col + 1];
            int r0 = m * 16 + g, r1 = m * 16 + 8 + g;
            float v00 = fmaxf(d[m][t][0] + bb0, 0.f), v01 = fmaxf(d[m][t][1] + bb1, 0.f);
            float v10 = fmaxf(d[m][t][2] + bb0, 0.f), v11 = fmaxf(d[m][t][3] + bb1, 0.f);
            __half x;
            x = __float2half(v00); h2h[r0 * 136 + col] = x; h2l[r0 * 136 + col] = __float2half(v00 - __half2float(x));
            x = __float2half(v01); h2h[r0 * 136 + col + 1] = x; h2l[r0 * 136 + col + 1] = __float2half(v01 - __half2float(x));
            x = __float2half(v10); h2h[r1 * 136 + col] = x; h2l[r1 * 136 + col] = __float2half(v10 - __half2float(x));
            x = __float2half(v11); h2h[r1 * 136 + col + 1] = x; h2l[r1 * 136 + col + 1] = __float2half(v11 - __half2float(x));
        }
    __syncthreads();

    // ---- layer 3: 128 -> 64 ----
    #pragma unroll
    for (int m = 0; m < 2; m++)
        #pragma unroll
        for (int t = 0; t < 2; t++) { d[m][t][0] = d[m][t][1] = d[m][t][2] = d[m][t][3] = 0.f; }
    for (int kt = 0; kt < 8; kt++) {
        int k0 = kt * 16;
        uint2 bh[2], bl[2];
        #pragma unroll
        for (int t = 0; t < 2; t++) {
            int fi = ((kt * 8 + warp * 2 + t) << 5) + lane;
            bh[t] = __ldg(&g_w3f_h[fi]);
            bl[t] = __ldg(&g_w3f_l[fi]);
        }
        #pragma unroll
        for (int m = 0; m < 2; m++) {
            int r0 = m * 16 + g, r1 = m * 16 + 8 + g;
            u32 ah0 = *(const u32*)&h2h[r0 * 136 + k0 + tq * 2];
            u32 ah1 = *(const u32*)&h2h[r1 * 136 + k0 + tq * 2];
            u32 ah2 = *(const u32*)&h2h[r0 * 136 + k0 + 8 + tq * 2];
            u32 ah3 = *(const u32*)&h2h[r1 * 136 + k0 + 8 + tq * 2];
            u32 al0 = *(const u32*)&h2l[r0 * 136 + k0 + tq * 2];
            u32 al1 = *(const u32*)&h2l[r1 * 136 + k0 + tq * 2];
            u32 al2 = *(const u32*)&h2l[r0 * 136 + k0 + 8 + tq * 2];
            u32 al3 = *(const u32*)&h2l[r1 * 136 + k0 + 8 + tq * 2];
            #pragma unroll
            for (int t = 0; t < 2; t++) {
                mma16816(d[m][t], ah0, ah1, ah2, ah3, bh[t].x, bh[t].y);
                mma16816(d[m][t], ah0, ah1, ah2, ah3, bl[t].x, bl[t].y);
                mma16816(d[m][t], al0, al1, al2, al3, bh[t].x, bh[t].y);
            }
        }
    }
    #pragma unroll
    for (int m = 0; m < 2; m++)
        #pragma unroll
        for (int t = 0; t < 2; t++) {
            int col = warp * 16 + t * 8 + tq * 2;
            float bb0 = b3[col], bb1 = b3[col + 1];
            int r0 = m * 16 + g, r1 = m * 16 + 8 + g;
            h3s[r0 * 64 + col]     = fmaxf(d[m][t][0] + bb0, 0.f);
            h3s[r0 * 64 + col + 1] = fmaxf(d[m][t][1] + bb1, 0.f);
            h3s[r1 * 64 + col]     = fmaxf(d[m][t][2] + bb0, 0.f);
            h3s[r1 * 64 + col + 1] = fmaxf(d[m][t][3] + bb1, 0.f);
        }
    __syncthreads();

    // ---- layer 4: 64 -> 2, * scale ----
    if (tid < 64) {
        int nn = tid >> 1, o = tid & 1;
        int n = n0 + nn;
        if (n < N_NODES) {
            float a = b4[o];
            const float* wrow = &w4[o * 64];
            #pragma unroll 8
            for (int c = 0; c < 64; c++) a += h3s[nn * 64 + c] * wrow[c];
            out[(size_t)n * 2 + o] = a * scale[o];
        }
    }
}

// ---------------- launch ----------------
extern "C" void kernel_launch(void* const* d_in, const int* in_sizes, int n_in,
                              void* d_out, int out_size) {
    const float* x     = (const float*)d_in[0];
    const float* pos   = (const float*)d_in[1];
    const int*   ei    = (const int*)d_in[2];
    const float* W0    = (const float*)d_in[3];
    const float* Ws    = (const float*)d_in[4];
    const float* ln_g  = (const float*)d_in[5];
    const float* ln_b  = (const float*)d_in[6];
    const float* w1    = (const float*)d_in[7];
    const float* b1    = (const float*)d_in[8];
    const float* w2    = (const float*)d_in[9];
    const float* b2    = (const float*)d_in[10];
    const float* w3    = (const float*)d_in[11];
    const float* b3    = (const float*)d_in[12];
    const float* w4    = (const float*)d_in[13];
    const float* b4    = (const float*)d_in[14];
    const float* scale = (const float*)d_in[15];
    float* out = (float*)d_out;

    cudaFuncSetAttribute(k_mlp, cudaFuncAttributeMaxDynamicSharedMemorySize, SMEM_MLP);

    const int TGRID = (N_NODES + 31) / 32;  // 1563

    k_hist<<<(N_EDGES + 255) / 256, 256>>>(ei);                    // #1
    k_quant_prep<<<69, 256>>>(W0, Ws, w1, w2, w3);                 // #2
    k_scan_local<<<SCAN_BLK, 512>>>();                             // #3
    k_transform0<<<TGRID, 256>>>(x, pos);                          // #4  <- profiled
    k_scan_add<<<SCAN_BLK, 512>>>();                               // #5
    k_scatter<<<(N_EDGES + 255) / 256, 256>>>(ei);                 // #6
    k_aggregate<<<N_NODES / 16, 256>>>(pos, ln_g, ln_b, 0, 4);     // #7

    for (int i = 1; i < 5; i++) {
        k_transform<<<TGRID, 256>>>(pos, i);
        k_aggregate<<<N_NODES / 16, 256>>>(pos, ln_g, ln_b, i, 67);
    }

    k_mlp<<<TGRID, 128, SMEM_MLP>>>(b1, b2, b3, w4, b4, scale, out);
}

// round 17
// speedup vs baseline: 1.0795x; 1.0087x over previous
#include <cuda_runtime.h>
#include <cuda_bf16.h>
#include <cuda_fp16.h>
#include <cfloat>
#include <cstdint>

#define N_NODES 50000
#define N_EDGES 800000
#define HID 64
#define ZDIM 320
#define WSTRIDE 68                 // padded W row (64x68, zeros in pad)
#define WSZ (64 * WSTRIDE)
#define SCAN_BLK 98                // ceil(50000/512)
#define NPADZ 50016                // pad g_z rows for 32-node MLP tiles

typedef unsigned long long ull;
typedef uint32_t u32;

// ---------------- device scratch ----------------
__device__ __half g_uh[N_NODES * HID];     // u stored fp16 (gather payload)
__device__ float g_z[NPADZ * ZDIM];        // pad rows never written -> zero
__device__ int   g_cnt[N_NODES];           // INVARIANT: all-zero at kernel_launch entry
__device__ int   g_off[N_NODES + 1];
__device__ int   g_cur[N_NODES];
__device__ int   g_csr[N_EDGES];
__device__ int   g_bsum[SCAN_BLK];
__device__ float g_Wq[5 * WSZ];            // all 5 quantized layer weights
// HMMA fragment-ordered weights (hi/lo fp16 split):
__device__ uint2 g_w1f_h[20 * 16 * 32], g_w1f_l[20 * 16 * 32];   // 320->128
__device__ uint2 g_w2f_h[8 * 16 * 32],  g_w2f_l[8 * 16 * 32];    // 128->128
__device__ uint2 g_w3f_h[8 * 8 * 32],   g_w3f_l[8 * 8 * 32];     // 128->64

// ---------------- f32x2 helpers ----------------
__device__ __forceinline__ ull fma2(ull a, ull b, ull c) {
    ull d;
    asm("fma.rn.f32x2 %0, %1, %2, %3;" : "=l"(d) : "l"(a), "l"(b), "l"(c));
    return d;
}
__device__ __forceinline__ float sum2(ull a) {
    float lo, hi;
    asm("mov.b64 {%0, %1}, %2;" : "=f"(lo), "=f"(hi) : "l"(a));
    return lo + hi;
}

// ---------------- mma.sync m16n8k16 f16 helper ----------------
__device__ __forceinline__ void mma16816(float* d, u32 a0, u32 a1, u32 a2, u32 a3,
                                         u32 b0, u32 b1) {
    asm volatile(
        "mma.sync.aligned.m16n8k16.row.col.f32.f16.f16.f32 "
        "{%0,%1,%2,%3}, {%4,%5,%6,%7}, {%8,%9}, {%0,%1,%2,%3};"
        : "+f"(d[0]), "+f"(d[1]), "+f"(d[2]), "+f"(d[3])
        : "r"(a0), "r"(a1), "r"(a2), "r"(a3), "r"(b0), "r"(b1));
}

__device__ __forceinline__ u32 packh2(float a, float b) {
    __half2 h = __floats2half2_rn(a, b);
    return *(u32*)&h;
}

#define H2(u) (*(__half2*)&(u))

// ---------------- prep: hist (0..3124) + fake-quant (3125..3129) + fragments (3130..3198) ----------------
__global__ void k_prep(const int* __restrict__ ei,
                       const float* __restrict__ W0, const float* __restrict__ Ws,
                       const float* __restrict__ w1, const float* __restrict__ w2,
                       const float* __restrict__ w3) {
    int blk = blockIdx.x, tid = threadIdx.x;
    if (blk < 3125) {
        int e = blk * 256 + tid;
        if (e < N_EDGES) atomicAdd(&g_cnt[ei[N_EDGES + e]], 1);
        return;
    }
    if (blk < 3130) {
        int b = blk - 3125;
        __shared__ float red[256];
        const float* W = (b == 0) ? W0 : (Ws + (size_t)(b - 1) * 64 * 67);
        int cols = (b == 0) ? 4 : 67;
        int n = 64 * cols;
        float* dst = g_Wq + b * WSZ;

        float m = 0.f;
        for (int i = tid; i < n; i += 256) m = fmaxf(m, fabsf(W[i]));
        red[tid] = m;
        __syncthreads();
        for (int s = 128; s > 0; s >>= 1) {
            if (tid < s) red[tid] = fmaxf(red[tid], red[tid + s]);
            __syncthreads();
        }
        float sc = fmaxf(red[0] * (1.0f / 127.0f), 1e-8f);
        for (int i = tid; i < WSZ; i += 256) dst[i] = 0.0f;
        __syncthreads();
        for (int i = tid; i < n; i += 256) {
            int k = i / cols, c = i % cols;
            float q = rintf(W[i] / sc);
            q = fminf(fmaxf(q, -127.0f), 127.0f) * sc;
            dst[k * WSTRIDE + c] = q;
        }
        return;
    }
    int idx = (blk - 3130) * 256 + tid;
    const float* src;
    uint2 *dh, *dl;
    int K, slot;
    if (idx < 10240)      { src = w1; dh = g_w1f_h; dl = g_w1f_l; K = 320; slot = idx;
                            int kt = slot >> 9, rem = slot & 511, nb = rem >> 5, lane = rem & 31;
                            int g = lane >> 2, tq = lane & 3;
                            int n = nb * 8 + g, kb = kt * 16 + tq * 2;
                            float v0 = src[n * K + kb],     v1 = src[n * K + kb + 1];
                            float v2 = src[n * K + kb + 8], v3 = src[n * K + kb + 9];
                            __half h0 = __float2half(v0), h1 = __float2half(v1);
                            __half h2 = __float2half(v2), h3 = __float2half(v3);
                            dh[slot] = make_uint2(packh2(__half2float(h0), __half2float(h1)),
                                                  packh2(__half2float(h2), __half2float(h3)));
                            dl[slot] = make_uint2(packh2(v0 - __half2float(h0), v1 - __half2float(h1)),
                                                  packh2(v2 - __half2float(h2), v3 - __half2float(h3)));
    } else if (idx < 14336) { src = w2; dh = g_w2f_h; dl = g_w2f_l; K = 128; slot = idx - 10240;
                            int kt = slot >> 9, rem = slot & 511, nb = rem >> 5, lane = rem & 31;
                            int g = lane >> 2, tq = lane & 3;
                            int n = nb * 8 + g, kb = kt * 16 + tq * 2;
                            float v0 = src[n * K + kb],     v1 = src[n * K + kb + 1];
                            float v2 = src[n * K + kb + 8], v3 = src[n * K + kb + 9];
                            __half h0 = __float2half(v0), h1 = __float2half(v1);
                            __half h2 = __float2half(v2), h3 = __float2half(v3);
                            dh[slot] = make_uint2(packh2(__half2float(h0), __half2float(h1)),
                                                  packh2(__half2float(h2), __half2float(h3)));
                            dl[slot] = make_uint2(packh2(v0 - __half2float(h0), v1 - __half2float(h1)),
                                                  packh2(v2 - __half2float(h2), v3 - __half2float(h3)));
    } else if (idx < 16384) { src = w3; dh = g_w3f_h; dl = g_w3f_l; K = 128; slot = idx - 14336;
                            int kt = slot >> 8, rem = slot & 255, nb = rem >> 5, lane = rem & 31;
                            int g = lane >> 2, tq = lane & 3;
                            int n = nb * 8 + g, kb = kt * 16 + tq * 2;
                            float v0 = src[n * K + kb],     v1 = src[n * K + kb + 1];
                            float v2 = src[n * K + kb + 8], v3 = src[n * K + kb + 9];
                            __half h0 = __float2half(v0), h1 = __float2half(v1);
                            __half h2 = __float2half(v2), h3 = __float2half(v3);
                            dh[slot] = make_uint2(packh2(__half2float(h0), __half2float(h1)),
                                                  packh2(__half2float(h2), __half2float(h3)));
                            dl[slot] = make_uint2(packh2(v0 - __half2float(h0), v1 - __half2float(h1)),
                                                  packh2(v2 - __half2float(h2), v3 - __half2float(h3)));
    }
}

// ---------------- CSR scan ----------------
__global__ void k_scan_local() {
    __shared__ int wsums[16];
    int b = blockIdx.x, tid = threadIdx.x, lane = tid & 31, wid = tid >> 5;
    int i = b * 512 + tid;
    int v = (i < N_NODES) ? g_cnt[i] : 0;
    int x = v;
    #pragma unroll
    for (int o = 1; o < 32; o <<= 1) {
        int y = __shfl_up_sync(0xffffffffu, x, o);
        if (lane >= o) x += y;
    }
    if (lane == 31) wsums[wid] = x;
    __syncthreads();
    if (wid == 0 && lane < 16) {
        int w = wsums[lane];
        int xs = w;
        #pragma unroll
        for (int o = 1; o < 16; o <<= 1) {
            int y = __shfl_up_sync(0xffffu, xs, o);
            if (lane >= o) xs += y;
        }
        wsums[lane] = xs - w;
    }
    __syncthreads();
    int excl = x - v + wsums[wid];
    if (i < N_NODES) g_off[i] = excl;
    if (tid == 511) g_bsum[b] = excl + v;
}

__global__ void k_scan_add() {
    __shared__ int part[4];
    int b = blockIdx.x, tid = threadIdx.x, lane = tid & 31, wid = tid >> 5;
    int v = 0;
    if (tid < b) v = g_bsum[tid];      // b <= 97 < 128
    if (tid < 128) {
        #pragma unroll
        for (int o = 16; o > 0; o >>= 1) v += __shfl_xor_sync(0xffffffffu, v, o);
        if (lane == 0) part[wid] = v;
    }
    __syncthreads();
    int add = part[0] + part[1] + part[2] + part[3];
    int i = b * 512 + tid;
    if (i < N_NODES) {
        int o = g_off[i] + add;
        g_off[i] = o;
        g_cur[i] = o;
        g_cnt[i] = 0;   // restore zero-invariant for next replay
    }
    if (i == 0) g_off[N_NODES] = N_EDGES;
}

__global__ void k_scatter(const int* __restrict__ ei) {
    int e = blockIdx.x * blockDim.x + threadIdx.x;
    if (e < N_EDGES) {
        int d = ei[N_EDGES + e];
        int p = atomicAdd(&g_cur[d], 1);
        g_csr[p] = ei[e];
    }
}

// ---------------- layer-0 transform ----------------
__global__ __launch_bounds__(256) void k_transform0(const float* __restrict__ x,
                                                    const float* __restrict__ pos) {
    __shared__ float4 Wsh[64];
    __shared__ float  xs[32];
    __shared__ float  ps[96];
    int tid = threadIdx.x;
    int nbase = blockIdx.x * 32;
    if (tid < 64) {
        const float* wr = g_Wq + tid * WSTRIDE;
        Wsh[tid] = make_float4(wr[0], wr[1], wr[2], wr[3]);
    } else if (tid < 96) {
        int n = nbase + (tid - 64);
        xs[tid - 64] = (n < N_NODES) ? x[n] : 0.f;
    } else if (tid < 192) {
        int j = tid - 96;
        int gi = nbase * 3 + j;
        ps[j] = (gi < N_NODES * 3) ? pos[gi] : 0.f;
    }
    __syncthreads();
    int k = tid & 63, grp = tid >> 6;
    float4 w = Wsh[k];
    #pragma unroll
    for (int j = 0; j < 8; j++) {
        int nn = grp * 8 + j;
        int n = nbase + nn;
        if (n < N_NODES) {
            float r = w.x * xs[nn] + w.y * ps[3 * nn] + w.z * ps[3 * nn + 1] + w.w * ps[3 * nn + 2];
            g_uh[(size_t)n * HID + k] = __float2half(r);
        }
    }
}

// ---------------- layers 1-4 transform ----------------
__global__ __launch_bounds__(256) void k_transform(const float* __restrict__ pos, int layer) {
    constexpr int C4 = 17;
    __shared__ float Wsh[WSZ];
    __shared__ float fsh[32][WSTRIDE];
    int tid = threadIdx.x;
    int k = tid & 63, grp = tid >> 6;
    const float* Wsrc = g_Wq + layer * WSZ;
    {
        const float4* s4 = (const float4*)Wsrc;
        float4* d4 = (float4*)Wsh;
        #pragma unroll
        for (int i = tid; i < WSZ / 4; i += 256) d4[i] = s4[i];
    }
    int nbase = blockIdx.x * 32;
    const float* h = g_z + (size_t)(layer - 1) * HID;
    #pragma unroll
    for (int i = tid; i < 32 * 64; i += 256) {
        int nn = i >> 6, c = i & 63;
        int gn = nbase + nn;
        fsh[nn][c] = (gn < N_NODES) ? h[(size_t)gn * ZDIM + c] : 0.f;
    }
    if (tid < 128) {
        int nn = tid >> 2, j = tid & 3;
        int gn = nbase + nn;
        float v = 0.f;
        if (j < 3 && gn < N_NODES) v = pos[gn * 3 + j];
        fsh[nn][64 + j] = v;
    }
    __syncthreads();
    ull w2r[C4 * 2];
    #pragma unroll
    for (int c4 = 0; c4 < C4; c4++) {
        ulonglong2 wv = *(const ulonglong2*)&Wsh[k * WSTRIDE + 4 * c4];
        w2r[2 * c4] = wv.x; w2r[2 * c4 + 1] = wv.y;
    }
    ull acc[8];
    #pragma unroll
    for (int j = 0; j < 8; j++) acc[j] = 0;
    #pragma unroll
    for (int c4 = 0; c4 < C4; c4++) {
        ull w01 = w2r[2 * c4], w23 = w2r[2 * c4 + 1];
        #pragma unroll
        for (int j = 0; j < 8; j++) {
            ulonglong2 f = *(const ulonglong2*)&fsh[grp * 8 + j][4 * c4];
            acc[j] = fma2(f.x, w01, acc[j]);
            acc[j] = fma2(f.y, w23, acc[j]);
        }
    }
    #pragma unroll
    for (int j = 0; j < 8; j++) {
        int n = nbase + grp * 8 + j;
        if (n < N_NODES) g_uh[(size_t)n * HID + k] = __float2half(sum2(acc[j]));
    }
}

// ---------------- aggregation: 4 nodes/warp, 8 lanes x uint4 (16B/lane) ----------------
__global__ __launch_bounds__(256) void k_aggregate(const float* __restrict__ pos,
                                                   const float* __restrict__ ln_g,
                                                   const float* __restrict__ ln_b,
                                                   int layer, int cols) {
    __shared__ float Wp[64][3];
    __shared__ float gs[64], bs[64];
    int tid = threadIdx.x;
    if (tid < 64) { gs[tid] = ln_g[layer * 64 + tid]; bs[tid] = ln_b[layer * 64 + tid]; }
    const float* Wsrc = g_Wq + layer * WSZ;
    for (int i = tid; i < 192; i += 256) {
        int k = i / 3, j = i % 3;
        Wp[k][j] = Wsrc[k * WSTRIDE + (cols - 3) + j];
    }
    __syncthreads();

    int wid = tid >> 5, lane = tid & 31;
    int quarter = lane >> 3, l8 = lane & 7;
    int n = blockIdx.x * 32 + wid * 4 + quarter;       // 32 nodes/block
    int s = 0, e = 0;
    if (n < N_NODES) { s = g_off[n]; e = g_off[n + 1]; }
    const uint4* ubase = (const uint4*)g_uh;            // row = 8 uint4 (64 halfs)

    __half2 M0 = __float2half2_rn(-65504.f);
    __half2 M1 = M0, M2 = M0, M3 = M0;
    int p = s;
    for (; p + 8 <= e; p += 8) {
        int i0 = g_csr[p],     i1 = g_csr[p + 1], i2 = g_csr[p + 2], i3 = g_csr[p + 3];
        int i4 = g_csr[p + 4], i5 = g_csr[p + 5], i6 = g_csr[p + 6], i7 = g_csr[p + 7];
        uint4 a = __ldcg(&ubase[(size_t)i0 * 8 + l8]);
        uint4 b = __ldcg(&ubase[(size_t)i1 * 8 + l8]);
        uint4 c = __ldcg(&ubase[(size_t)i2 * 8 + l8]);
        uint4 d = __ldcg(&ubase[(size_t)i3 * 8 + l8]);
        uint4 f = __ldcg(&ubase[(size_t)i4 * 8 + l8]);
        uint4 g = __ldcg(&ubase[(size_t)i5 * 8 + l8]);
        uint4 h = __ldcg(&ubase[(size_t)i6 * 8 + l8]);
        uint4 q = __ldcg(&ubase[(size_t)i7 * 8 + l8]);
        M0 = __hmax2(M0, __hmax2(__hmax2(H2(a.x), H2(b.x)), __hmax2(H2(c.x), H2(d.x))));
        M0 = __hmax2(M0, __hmax2(__hmax2(H2(f.x), H2(g.x)), __hmax2(H2(h.x), H2(q.x))));
        M1 = __hmax2(M1, __hmax2(__hmax2(H2(a.y), H2(b.y)), __hmax2(H2(c.y), H2(d.y))));
        M1 = __hmax2(M1, __hmax2(__hmax2(H2(f.y), H2(g.y)), __hmax2(H2(h.y), H2(q.y))));
        M2 = __hmax2(M2, __hmax2(__hmax2(H2(a.z), H2(b.z)), __hmax2(H2(c.z), H2(d.z))));
        M2 = __hmax2(M2, __hmax2(__hmax2(H2(f.z), H2(g.z)), __hmax2(H2(h.z), H2(q.z))));
        M3 = __hmax2(M3, __hmax2(__hmax2(H2(a.w), H2(b.w)), __hmax2(H2(c.w), H2(d.w))));
        M3 = __hmax2(M3, __hmax2(__hmax2(H2(f.w), H2(g.w)), __hmax2(H2(h.w), H2(q.w))));
    }
    for (; p + 4 <= e; p += 4) {
        int i0 = g_csr[p], i1 = g_csr[p + 1], i2 = g_csr[p + 2], i3 = g_csr[p + 3];
        uint4 a = __ldcg(&ubase[(size_t)i0 * 8 + l8]);
        uint4 b = __ldcg(&ubase[(size_t)i1 * 8 + l8]);
        uint4 c = __ldcg(&ubase[(size_t)i2 * 8 + l8]);
        uint4 d = __ldcg(&ubase[(size_t)i3 * 8 + l8]);
        M0 = __hmax2(M0, __hmax2(__hmax2(H2(a.x), H2(b.x)), __hmax2(H2(c.x), H2(d.x))));
        M1 = __hmax2(M1, __hmax2(__hmax2(H2(a.y), H2(b.y)), __hmax2(H2(c.y), H2(d.y))));
        M2 = __hmax2(M2, __hmax2(__hmax2(H2(a.z), H2(b.z)), __hmax2(H2(c.z), H2(d.z))));
        M3 = __hmax2(M3, __hmax2(__hmax2(H2(a.w), H2(b.w)), __hmax2(H2(c.w), H2(d.w))));
    }
    for (; p < e; p++) {
        int i0 = g_csr[p];
        uint4 a = __ldcg(&ubase[(size_t)i0 * 8 + l8]);
        M0 = __hmax2(M0, H2(a.x));
        M1 = __hmax2(M1, H2(a.y));
        M2 = __hmax2(M2, H2(a.z));
        M3 = __hmax2(M3, H2(a.w));
    }

    float2 f0 = __half22float2(M0);
    float2 f1 = __half22float2(M1);
    float2 f2 = __half22float2(M2);
    float2 f3 = __half22float2(M3);
    float mv[8] = {f0.x, f0.y, f1.x, f1.y, f2.x, f2.y, f3.x, f3.y};

    float px = 0.f, py = 0.f, pz = 0.f;
    if (n < N_NODES) { px = pos[n * 3 + 0]; py = pos[n * 3 + 1]; pz = pos[n * 3 + 2]; }
    int k0 = 8 * l8;
    float hh[8];
    #pragma unroll
    for (int j = 0; j < 8; j++) {
        float v = px * Wp[k0 + j][0] + py * Wp[k0 + j][1] + pz * Wp[k0 + j][2];
        hh[j] = (e > s) ? (mv[j] - v) : 0.f;
    }

    // LayerNorm over 64 channels within the 8-lane group
    float sum = 0.f, sq = 0.f;
    #pragma unroll
    for (int j = 0; j < 8; j++) { sum += hh[j]; sq += hh[j] * hh[j]; }
    #pragma unroll
    for (int o = 4; o > 0; o >>= 1) {
        sum += __shfl_xor_sync(0xffffffffu, sum, o);
        sq  += __shfl_xor_sync(0xffffffffu, sq, o);
    }
    float mean = sum * (1.0f / 64.0f);
    float var  = fmaxf(sq * (1.0f / 64.0f) - mean * mean, 0.f);
    float rstd = rsqrtf(var + 1e-5f);
    float o8[8];
    #pragma unroll
    for (int j = 0; j < 8; j++)
        o8[j] = fmaxf((hh[j] - mean) * rstd * gs[k0 + j] + bs[k0 + j], 0.f);
    if (n < N_NODES) {
        float* zp = &g_z[(size_t)n * ZDIM + layer * 64 + k0];
        *(float4*)zp       = make_float4(o8[0], o8[1], o8[2], o8[3]);
        *(float4*)(zp + 4) = make_float4(o8[4], o8[5], o8[6], o8[7]);
    }
}

// ---------------- MLP via HMMA, 32-node tile, fragment-ordered weights ----------------
#define OZH  0
#define OZL  20992
#define OH1H 41984
#define OH1L 50688
#define OH2H 59392
#define OH2L 68096
#define OH3  76800
#define OST  84992
#define SMEM_MLP 85248

__global__ __launch_bounds__(128) void k_mlp(const float* __restrict__ b1,
                                             const float* __restrict__ b2,
                                             const float* __restrict__ b3,
                                             const float* __restrict__ w4,
                                             const float* __restrict__ b4,
                                             const float* __restrict__ scale,
                                             float* __restrict__ out) {
    extern __shared__ char sm[];
    __half* zh  = (__half*)(sm + OZH);
    __half* zl  = (__half*)(sm + OZL);
    __half* h1h = (__half*)(sm + OH1H);
    __half* h1l = (__half*)(sm + OH1L);
    __half* h2h = (__half*)(sm + OH2H);
    __half* h2l = (__half*)(sm + OH2L);
    float*  h3s = (float*)(sm + OH3);
    float*  meansh = (float*)(sm + OST);
    float*  rstdsh = (float*)(sm + OST + 128);

    int tid = threadIdx.x;
    int n0 = blockIdx.x * 32;
    int warp = tid >> 5, lane = tid & 31;
    int g = lane >> 2, tq = lane & 3;

    {
        int node = warp * 8 + (lane >> 2), j = lane & 3;
        const float4* zr = (const float4*)&g_z[(size_t)(n0 + node) * ZDIM];
        float s = 0.f, sq = 0.f;
        for (int i = j; i < 80; i += 4) {
            float4 v = zr[i];
            s += v.x + v.y + v.z + v.w;
            sq += v.x * v.x + v.y * v.y + v.z * v.z + v.w * v.w;
        }
        s  += __shfl_down_sync(0xffffffffu, s, 2, 4);
        s  += __shfl_down_sync(0xffffffffu, s, 1, 4);
        sq += __shfl_down_sync(0xffffffffu, sq, 2, 4);
        sq += __shfl_down_sync(0xffffffffu, sq, 1, 4);
        if (j == 0) {
            float mean = s * (1.0f / 320.0f);
            float var  = fmaxf(sq * (1.0f / 320.0f) - mean * mean, 0.f);
            meansh[node] = mean;
            rstdsh[node] = rsqrtf(var + 1e-5f);
        }
    }
    __syncthreads();
    for (int i = tid; i < 32 * 320; i += 128) {
        int nn = i / 320, c = i - nn * 320;
        float v = (g_z[(size_t)(n0 + nn) * ZDIM + c] - meansh[nn]) * rstdsh[nn];
        __half h = __float2half(v);
        zh[nn * 328 + c] = h;
        zl[nn * 328 + c] = __float2half(v - __half2float(h));
    }
    __syncthreads();

    float d[2][4][4];

    // ---- layer 1: 320 -> 128 ----
    #pragma unroll
    for (int m = 0; m < 2; m++)
        #pragma unroll
        for (int t = 0; t < 4; t++) { d[m][t][0] = d[m][t][1] = d[m][t][2] = d[m][t][3] = 0.f; }
    for (int kt = 0; kt < 20; kt++) {
        int k0 = kt * 16;
        uint2 bh[4], bl[4];
        #pragma unroll
        for (int t = 0; t < 4; t++) {
            int fi = ((kt * 16 + warp * 4 + t) << 5) + lane;
            bh[t] = __ldg(&g_w1f_h[fi]);
            bl[t] = __ldg(&g_w1f_l[fi]);
        }
        #pragma unroll
        for (int m = 0; m < 2; m++) {
            int r0 = m * 16 + g, r1 = m * 16 + 8 + g;
            u32 ah0 = *(const u32*)&zh[r0 * 328 + k0 + tq * 2];
            u32 ah1 = *(const u32*)&zh[r1 * 328 + k0 + tq * 2];
            u32 ah2 = *(const u32*)&zh[r0 * 328 + k0 + 8 + tq * 2];
            u32 ah3 = *(const u32*)&zh[r1 * 328 + k0 + 8 + tq * 2];
            u32 al0 = *(const u32*)&zl[r0 * 328 + k0 + tq * 2];
            u32 al1 = *(const u32*)&zl[r1 * 328 + k0 + tq * 2];
            u32 al2 = *(const u32*)&zl[r0 * 328 + k0 + 8 + tq * 2];
            u32 al3 = *(const u32*)&zl[r1 * 328 + k0 + 8 + tq * 2];
            #pragma unroll
            for (int t = 0; t < 4; t++) {
                mma16816(d[m][t], ah0, ah1, ah2, ah3, bh[t].x, bh[t].y);
                mma16816(d[m][t], ah0, ah1, ah2, ah3, bl[t].x, bl[t].y);
                mma16816(d[m][t], al0, al1, al2, al3, bh[t].x, bh[t].y);
            }
        }
    }
    #pragma unroll
    for (int m = 0; m < 2; m++)
        #pragma unroll
        for (int t = 0; t < 4; t++) {
            int col = warp * 32 + t * 8 + tq * 2;
            float bb0 = b1[col], bb1 = b1[col + 1];
            int r0 = m * 16 + g, r1 = m * 16 + 8 + g;
            float v00 = fmaxf(d[m][t][0] + bb0, 0.f), v01 = fmaxf(d[m][t][1] + bb1, 0.f);
            float v10 = fmaxf(d[m][t][2] + bb0, 0.f), v11 = fmaxf(d[m][t][3] + bb1, 0.f);
            __half x;
            x = __float2half(v00); h1h[r0 * 136 + col] = x; h1l[r0 * 136 + col] = __float2half(v00 - __half2float(x));
            x = __float2half(v01); h1h[r0 * 136 + col + 1] = x; h1l[r0 * 136 + col + 1] = __float2half(v01 - __half2float(x));
            x = __float2half(v10); h1h[r1 * 136 + col] = x; h1l[r1 * 136 + col] = __float2half(v10 - __half2float(x));
            x = __float2half(v11); h1h[r1 * 136 + col + 1] = x; h1l[r1 * 136 + col + 1] = __float2half(v11 - __half2float(x));
        }
    __syncthreads();

    // ---- layer 2: 128 -> 128 ----
    #pragma unroll
    for (int m = 0; m < 2; m++)
        #pragma unroll
        for (int t = 0; t < 4; t++) { d[m][t][0] = d[m][t][1] = d[m][t][2] = d[m][t][3] = 0.f; }
    for (int kt = 0; kt < 8; kt++) {
        int k0 = kt * 16;
        uint2 bh[4], bl[4];
        #pragma unroll
        for (int t = 0; t < 4; t++) {
            int fi = ((kt * 16 + warp * 4 + t) << 5) + lane;
            bh[t] = __ldg(&g_w2f_h[fi]);
            bl[t] = __ldg(&g_w2f_l[fi]);
        }
        #pragma unroll
        for (int m = 0; m < 2; m++) {
            int r0 = m * 16 + g, r1 = m * 16 + 8 + g;
            u32 ah0 = *(const u32*)&h1h[r0 * 136 + k0 + tq * 2];
            u32 ah1 = *(const u32*)&h1h[r1 * 136 + k0 + tq * 2];
            u32 ah2 = *(const u32*)&h1h[r0 * 136 + k0 + 8 + tq * 2];
            u32 ah3 = *(const u32*)&h1h[r1 * 136 + k0 + 8 + tq * 2];
            u32 al0 = *(const u32*)&h1l[r0 * 136 + k0 + tq * 2];
            u32 al1 = *(const u32*)&h1l[r1 * 136 + k0 + tq * 2];
            u32 al2 = *(const u32*)&h1l[r0 * 136 + k0 + 8 + tq * 2];
            u32 al3 = *(const u32*)&h1l[r1 * 136 + k0 + 8 + tq * 2];
            #pragma unroll
            for (int t = 0; t < 4; t++) {
                mma16816(d[m][t], ah0, ah1, ah2, ah3, bh[t].x, bh[t].y);
                mma16816(d[m][t], ah0, ah1, ah2, ah3, bl[t].x, bl[t].y);
                mma16816(d[m][t], al0, al1, al2, al3, bh[t].x, bh[t].y);
            }
        }
    }
    #pragma unroll
    for (int m = 0; m < 2; m++)
        #pragma unroll
        for (int t = 0; t < 4; t++) {
            int col = warp * 32 + t * 8 + tq * 2;
            float bb0 = b2[col], bb1 = b2[col + 1];
            int r0 = m * 16 + g, r1 = m * 16 + 8 + g;
            float v00 = fmaxf(d[m][t][0] + bb0, 0.f), v01 = fmaxf(d[m][t][1] + bb1, 0.f);
            float v10 = fmaxf(d[m][t][2] + bb0, 0.f), v11 = fmaxf(d[m][t][3] + bb1, 0.f);
            __half x;
            x = __float2half(v00); h2h[r0 * 136 + col] = x; h2l[r0 * 136 + col] = __float2half(v00 - __half2float(x));
            x = __float2half(v01); h2h[r0 * 136 + col + 1] = x; h2l[r0 * 136 + col + 1] = __float2half(v01 - __half2float(x));
            x = __float2half(v10); h2h[r1 * 136 + col] = x; h2l[r1 * 136 + col] = __float2half(v10 - __half2float(x));
            x = __float2half(v11); h2h[r1 * 136 + col + 1] = x; h2l[r1 * 136 + col + 1] = __float2half(v11 - __half2float(x));
        }
    __syncthreads();

    // ---- layer 3: 128 -> 64 ----
    #pragma unroll
    for (int m = 0; m < 2; m++)
        #pragma unroll
        for (int t = 0; t < 2; t++) { d[m][t][0] = d[m][t][1] = d[m][t][2] = d[m][t][3] = 0.f; }
    for (int kt = 0; kt < 8; kt++) {
        int k0 = kt * 16;
        uint2 bh[2], bl[2];
        #pragma unroll
        for (int t = 0; t < 2; t++) {
            int fi = ((kt * 8 + warp * 2 + t) << 5) + lane;
            bh[t] = __ldg(&g_w3f_h[fi]);
            bl[t] = __ldg(&g_w3f_l[fi]);
        }
        #pragma unroll
        for (int m = 0; m < 2; m++) {
            int r0 = m * 16 + g, r1 = m * 16 + 8 + g;
            u32 ah0 = *(const u32*)&h2h[r0 * 136 + k0 + tq * 2];
            u32 ah1 = *(const u32*)&h2h[r1 * 136 + k0 + tq * 2];
            u32 ah2 = *(const u32*)&h2h[r0 * 136 + k0 + 8 + tq * 2];
            u32 ah3 = *(const u32*)&h2h[r1 * 136 + k0 + 8 + tq * 2];
            u32 al0 = *(const u32*)&h2l[r0 * 136 + k0 + tq * 2];
            u32 al1 = *(const u32*)&h2l[r1 * 136 + k0 + tq * 2];
            u32 al2 = *(const u32*)&h2l[r0 * 136 + k0 + 8 + tq * 2];
            u32 al3 = *(const u32*)&h2l[r1 * 136 + k0 + 8 + tq * 2];
            #pragma unroll
            for (int t = 0; t < 2; t++) {
                mma16816(d[m][t], ah0, ah1, ah2, ah3, bh[t].x, bh[t].y);
                mma16816(d[m][t], ah0, ah1, ah2, ah3, bl[t].x, bl[t].y);
                mma16816(d[m][t], al0, al1, al2, al3, bh[t].x, bh[t].y);
            }
        }
    }
    #pragma unroll
    for (int m = 0; m < 2; m++)
        #pragma unroll
        for (int t = 0; t < 2; t++) {
            int col = warp * 16 + t * 8 + tq * 2;
            float bb0 = b3[col], bb1 = b3[col + 1];
            int r0 = m * 16 + g, r1 = m * 16 + 8 + g;
            h3s[r0 * 64 + col]     = fmaxf(d[m][t][0] + bb0, 0.f);
            h3s[r0 * 64 + col + 1] = fmaxf(d[m][t][1] + bb1, 0.f);
            h3s[r1 * 64 + col]     = fmaxf(d[m][t][2] + bb0, 0.f);
            h3s[r1 * 64 + col + 1] = fmaxf(d[m][t][3] + bb1, 0.f);
        }
    __syncthreads();

    // ---- layer 4: 64 -> 2, * scale ----
    if (tid < 64) {
        int nn = tid >> 1, o = tid & 1;
        int n = n0 + nn;
        if (n < N_NODES) {
            float a = b4[o];
            const float* wrow = &w4[o * 64];
            #pragma unroll 8
            for (int c = 0; c < 64; c++) a += h3s[nn * 64 + c] * wrow[c];
            out[(size_t)n * 2 + o] = a * scale[o];
        }
    }
}

// ---------------- launch ----------------
extern "C" void kernel_launch(void* const* d_in, const int* in_sizes, int n_in,
                              void* d_out, int out_size) {
    const float* x     = (const float*)d_in[0];
    const float* pos   = (const float*)d_in[1];
    const int*   ei    = (const int*)d_in[2];
    const float* W0    = (const float*)d_in[3];
    const float* Ws    = (const float*)d_in[4];
    const float* ln_g  = (const float*)d_in[5];
    const float* ln_b  = (const float*)d_in[6];
    const float* w1    = (const float*)d_in[7];
    const float* b1    = (const float*)d_in[8];
    const float* w2    = (const float*)d_in[9];
    const float* b2    = (const float*)d_in[10];
    const float* w3    = (const float*)d_in[11];
    const float* b3    = (const float*)d_in[12];
    const float* w4    = (const float*)d_in[13];
    const float* b4    = (const float*)d_in[14];
    const float* scale = (const float*)d_in[15];
    float* out = (float*)d_out;

    cudaFuncSetAttribute(k_mlp, cudaFuncAttributeMaxDynamicSharedMemorySize, SMEM_MLP);

    const int TGRID = (N_NODES + 31) / 32;  // 1563

    k_prep<<<3194, 256>>>(ei, W0, Ws, w1, w2, w3);                 // #1 (hist + quant + frags)
    k_scan_local<<<SCAN_BLK, 512>>>();                             // #2
    k_scan_add<<<SCAN_BLK, 512>>>();                               // #3
    k_transform0<<<TGRID, 256>>>(x, pos);                          // #4  <- profiled
    k_scatter<<<(N_EDGES + 255) / 256, 256>>>(ei);                 // #5
    k_aggregate<<<TGRID, 256>>>(pos, ln_g, ln_b, 0, 4);            // #6

    for (int i = 1; i < 5; i++) {
        k_transform<<<TGRID, 256>>>(pos, i);
        k_aggregate<<<TGRID, 256>>>(pos, ln_g, ln_b, i, 67);
    }

    k_mlp<<<TGRID, 128, SMEM_MLP>>>(b1, b2, b3, w4, b4, scale, out);
}